// round 3
// baseline (speedup 1.0000x reference)
#include <cuda_runtime.h>
#include <cuda_bf16.h>
#include <math.h>

// Problem constants (fixed by the reference)
#define NN 50000
#define EE 800000
#define ET (EE + NN)          // edges + self loops
#define FIN 128
#define H1DIM 256             // 4 heads x 64
#define H2DIM 128             // 1 head x 128
#define NGRAPH 64
#define NEG_SLOPE 0.2f

// ---------------- scratch (static device globals; no allocation) -------------
__device__ __align__(16) float g_h1[(size_t)NN * H1DIM];     // x @ W1
__device__ __align__(16) float g_out1[(size_t)NN * H1DIM];   // after GAT1 + elu
__device__ __align__(16) float g_h2[(size_t)NN * H2DIM];     // out1 @ W2
__device__ __align__(16) float g_out2[(size_t)NN * H2DIM];   // after GAT2 + elu
__device__ float g_es1[NN * 4];
__device__ float g_ed1[NN * 4];
__device__ float g_es2[NN];
__device__ float g_ed2[NN];
__device__ int   g_cnt[NN];
__device__ int   g_off[NN + 1];
__device__ int   g_cur[NN];
__device__ int   g_esrc[ET];

// ---------------- CSR build --------------------------------------------------
__global__ void zero_counts_kernel() {
    int i = blockIdx.x * blockDim.x + threadIdx.x;
    if (i < NN) g_cnt[i] = 0;
}

__global__ void count_kernel(const int* __restrict__ ei) {
    int e = blockIdx.x * blockDim.x + threadIdx.x;
    if (e >= ET) return;
    int dst = (e < EE) ? ei[EE + e] : (e - EE);
    atomicAdd(&g_cnt[dst], 1);
}

__global__ void scan_kernel() {
    __shared__ int sdata[1024];
    __shared__ int s_carry;
    int tid = threadIdx.x;
    if (tid == 0) s_carry = 0;
    __syncthreads();
    for (int base = 0; base < NN; base += 1024) {
        int i = base + tid;
        int v = (i < NN) ? g_cnt[i] : 0;
        sdata[tid] = v;
        __syncthreads();
        #pragma unroll
        for (int d = 1; d < 1024; d <<= 1) {
            int t = (tid >= d) ? sdata[tid - d] : 0;
            __syncthreads();
            sdata[tid] += t;
            __syncthreads();
        }
        int carry = s_carry;
        if (i < NN) {
            g_off[i] = carry + sdata[tid] - v;  // exclusive
            g_cur[i] = carry + sdata[tid] - v;
        }
        __syncthreads();
        if (tid == 0) s_carry = carry + sdata[1023];
        __syncthreads();
    }
    if (tid == 0) g_off[NN] = s_carry;
}

__global__ void fill_kernel(const int* __restrict__ ei) {
    int e = blockIdx.x * blockDim.x + threadIdx.x;
    if (e >= ET) return;
    int src, dst;
    if (e < EE) { src = ei[e]; dst = ei[EE + e]; }
    else        { src = e - EE; dst = e - EE; }
    int pos = atomicAdd(&g_cur[dst], 1);
    g_esrc[pos] = src;
}

// ---------------- GEMM: C[M,N] = A[M,K] @ B[K,N] -----------------------------
#define BM 128
#define BN 128
#define BKK 8
__device__ __forceinline__ void gemm_body(
    const float* __restrict__ A, const float* __restrict__ B,
    float* __restrict__ C, int M, int N, int K)
{
    __shared__ float As[BKK][BM];
    __shared__ float Bs[BKK][BN];
    int tid = threadIdx.x;
    int bm = blockIdx.y * BM, bn = blockIdx.x * BN;
    int tx = tid & 15, ty = tid >> 4;
    float acc[8][8];
    #pragma unroll
    for (int i = 0; i < 8; i++)
        #pragma unroll
        for (int j = 0; j < 8; j++) acc[i][j] = 0.f;

    int arow = tid >> 1, acol = (tid & 1) * 4;
    int brow = tid >> 5, bcol = (tid & 31) * 4;

    for (int k0 = 0; k0 < K; k0 += BKK) {
        float4 av = make_float4(0.f, 0.f, 0.f, 0.f);
        if (bm + arow < M)
            av = *(const float4*)(A + (size_t)(bm + arow) * K + k0 + acol);
        As[acol + 0][arow] = av.x;
        As[acol + 1][arow] = av.y;
        As[acol + 2][arow] = av.z;
        As[acol + 3][arow] = av.w;
        float4 bv = *(const float4*)(B + (size_t)(k0 + brow) * N + bn + bcol);
        *(float4*)&Bs[brow][bcol] = bv;
        __syncthreads();
        #pragma unroll
        for (int kk = 0; kk < BKK; kk++) {
            float a[8], b[8];
            #pragma unroll
            for (int i = 0; i < 8; i++) a[i] = As[kk][ty * 8 + i];
            #pragma unroll
            for (int j = 0; j < 8; j++) b[j] = Bs[kk][tx * 8 + j];
            #pragma unroll
            for (int i = 0; i < 8; i++)
                #pragma unroll
                for (int j = 0; j < 8; j++)
                    acc[i][j] = fmaf(a[i], b[j], acc[i][j]);
        }
        __syncthreads();
    }
    #pragma unroll
    for (int i = 0; i < 8; i++) {
        int row = bm + ty * 8 + i;
        if (row >= M) continue;
        #pragma unroll
        for (int j = 0; j < 8; j += 4) {
            *(float4*)(C + (size_t)row * N + bn + tx * 8 + j) =
                make_float4(acc[i][j], acc[i][j + 1], acc[i][j + 2], acc[i][j + 3]);
        }
    }
}

// Wrappers bind __device__ scratch in device code (no host symbol queries)
__global__ __launch_bounds__(256) void gemm1_kernel(
    const float* __restrict__ x, const float* __restrict__ W1)
{
    gemm_body(x, W1, g_h1, NN, H1DIM, FIN);
}

__global__ __launch_bounds__(256) void gemm2_kernel(
    const float* __restrict__ W2)
{
    gemm_body(g_out1, W2, g_h2, NN, H2DIM, H1DIM);
}

// ---------------- attention coefficients ------------------------------------
__global__ void coef1_kernel(const float* __restrict__ a_s, const float* __restrict__ a_d) {
    int idx = blockIdx.x * blockDim.x + threadIdx.x;  // node*4 + head
    if (idx >= NN * 4) return;
    int node = idx >> 2, head = idx & 3;
    const float* row = g_h1 + (size_t)node * H1DIM + head * 64;
    const float* as = a_s + head * 64;
    const float* ad = a_d + head * 64;
    float s = 0.f, d = 0.f;
    #pragma unroll 16
    for (int c = 0; c < 64; c++) {
        float h = row[c];
        s = fmaf(h, as[c], s);
        d = fmaf(h, ad[c], d);
    }
    g_es1[idx] = s;
    g_ed1[idx] = d;
}

__global__ void coef2_kernel(const float* __restrict__ a_s, const float* __restrict__ a_d) {
    int node = blockIdx.x * blockDim.x + threadIdx.x;
    if (node >= NN) return;
    const float* row = g_h2 + (size_t)node * H2DIM;
    float s = 0.f, d = 0.f;
    #pragma unroll 16
    for (int c = 0; c < 128; c++) {
        float h = row[c];
        s = fmaf(h, a_s[c], s);
        d = fmaf(h, a_d[c], d);
    }
    g_es2[node] = s;
    g_ed2[node] = d;
}

__device__ __forceinline__ float elu1(float x) {
    return x > 0.f ? x : expm1f(x);
}

// ---------------- GAT layer 1 aggregation: warp per (dst, head) --------------
__global__ __launch_bounds__(256) void agg1_kernel(const float* __restrict__ b1) {
    int warp = (blockIdx.x * blockDim.x + threadIdx.x) >> 5;
    int lane = threadIdx.x & 31;
    if (warp >= NN * 4) return;
    int dst = warp >> 2, head = warp & 3;
    int start = g_off[dst], end = g_off[dst + 1];
    float edv = g_ed1[dst * 4 + head];
    float m = -1e30f, s = 0.f, acc0 = 0.f, acc1 = 0.f;
    for (int j = start; j < end; j++) {
        int src = g_esrc[j];
        float e = g_es1[src * 4 + head] + edv;
        e = (e > 0.f) ? e : NEG_SLOPE * e;
        float mn = fmaxf(m, e);
        float scale = __expf(m - mn);
        float w = __expf(e - mn);
        const float* hrow = g_h1 + (size_t)src * H1DIM + head * 64;
        acc0 = fmaf(w, hrow[lane],      acc0 * scale);
        acc1 = fmaf(w, hrow[lane + 32], acc1 * scale);
        s = fmaf(s, scale, w);
        m = mn;
    }
    float inv = 1.f / s;
    int o = head * 64 + lane;
    g_out1[(size_t)dst * H1DIM + o]      = elu1(acc0 * inv + b1[o]);
    g_out1[(size_t)dst * H1DIM + o + 32] = elu1(acc1 * inv + b1[o + 32]);
}

// ---------------- GAT layer 2 aggregation: warp per dst ----------------------
__global__ __launch_bounds__(256) void agg2_kernel(const float* __restrict__ b2) {
    int dst = (blockIdx.x * blockDim.x + threadIdx.x) >> 5;
    int lane = threadIdx.x & 31;
    if (dst >= NN) return;
    int start = g_off[dst], end = g_off[dst + 1];
    float edv = g_ed2[dst];
    float m = -1e30f, s = 0.f;
    float acc[4] = {0.f, 0.f, 0.f, 0.f};
    for (int j = start; j < end; j++) {
        int src = g_esrc[j];
        float e = g_es2[src] + edv;
        e = (e > 0.f) ? e : NEG_SLOPE * e;
        float mn = fmaxf(m, e);
        float scale = __expf(m - mn);
        float w = __expf(e - mn);
        const float* hrow = g_h2 + (size_t)src * H2DIM;
        #pragma unroll
        for (int r = 0; r < 4; r++)
            acc[r] = fmaf(w, hrow[lane + 32 * r], acc[r] * scale);
        s = fmaf(s, scale, w);
        m = mn;
    }
    float inv = 1.f / s;
    #pragma unroll
    for (int r = 0; r < 4; r++) {
        int o = lane + 32 * r;
        g_out2[(size_t)dst * H2DIM + o] = elu1(acc[r] * inv + b2[o]);
    }
}

// ---------------- pooling + FC + log_softmax ---------------------------------
__device__ __forceinline__ int lb_i(const int* a, int n, int v) {
    int lo = 0, hi = n;
    while (lo < hi) { int mid = (lo + hi) >> 1; if (a[mid] < v) lo = mid + 1; else hi = mid; }
    return lo;
}

__global__ void pool_fc_kernel(const int* __restrict__ batch,
                               const float* __restrict__ fc_w,
                               const float* __restrict__ fc_b,
                               float* __restrict__ out)
{
    int g = blockIdx.x;   // 64 blocks, 128 threads
    int tid = threadIdx.x;
    __shared__ float sp[128];
    __shared__ float slog[10];
    int lo = lb_i(batch, NN, g);
    int hi = lb_i(batch, NN, g + 1);
    float s = 0.f;
    for (int i = lo; i < hi; i++) s += g_out2[(size_t)i * H2DIM + tid];
    float cnt = (float)(hi - lo);
    sp[tid] = s / fmaxf(cnt, 1.f);
    __syncthreads();
    if (tid < 10) {
        float l = fc_b[tid];
        #pragma unroll 16
        for (int c = 0; c < 128; c++) l = fmaf(sp[c], fc_w[c * 10 + tid], l);
        slog[tid] = l;
    }
    __syncthreads();
    if (tid == 0) {
        float mx = -1e30f;
        #pragma unroll
        for (int k = 0; k < 10; k++) mx = fmaxf(mx, slog[k]);
        float sum = 0.f;
        #pragma unroll
        for (int k = 0; k < 10; k++) sum += expf(slog[k] - mx);
        float lse = mx + logf(sum);
        #pragma unroll
        for (int k = 0; k < 10; k++) out[g * 10 + k] = slog[k] - lse;
    }
}

// ---------------- launch -----------------------------------------------------
extern "C" void kernel_launch(void* const* d_in, const int* in_sizes, int n_in,
                              void* d_out, int out_size)
{
    const float* x     = (const float*)d_in[0];
    const int*   ei    = (const int*)d_in[1];      // int32 (JAX x64 disabled)
    const int*   batch = (const int*)d_in[2];      // int32
    const float* W1    = (const float*)d_in[3];
    const float* a_s1  = (const float*)d_in[4];
    const float* a_d1  = (const float*)d_in[5];
    const float* b1    = (const float*)d_in[6];
    const float* W2    = (const float*)d_in[7];
    const float* a_s2  = (const float*)d_in[8];
    const float* a_d2  = (const float*)d_in[9];
    const float* b2    = (const float*)d_in[10];
    const float* fc_w  = (const float*)d_in[11];
    const float* fc_b  = (const float*)d_in[12];
    float* out = (float*)d_out;

    // CSR build (shared by both layers)
    zero_counts_kernel<<<(NN + 255) / 256, 256>>>();
    count_kernel<<<(ET + 255) / 256, 256>>>(ei);
    scan_kernel<<<1, 1024>>>();
    fill_kernel<<<(ET + 255) / 256, 256>>>(ei);

    // Layer 1: h1 = x @ W1
    {
        dim3 grid(H1DIM / BN, (NN + BM - 1) / BM);
        gemm1_kernel<<<grid, 256>>>(x, W1);
    }
    coef1_kernel<<<(NN * 4 + 255) / 256, 256>>>(a_s1, a_d1);
    agg1_kernel<<<(NN * 4 * 32 + 255) / 256, 256>>>(b1);

    // Layer 2: h2 = out1 @ W2
    {
        dim3 grid(H2DIM / BN, (NN + BM - 1) / BM);
        gemm2_kernel<<<grid, 256>>>(W2);
    }
    coef2_kernel<<<(NN + 255) / 256, 256>>>(a_s2, a_d2);
    agg2_kernel<<<(NN * 32 + 255) / 256, 256>>>(b2);

    // Pool + FC + log_softmax
    pool_fc_kernel<<<NGRAPH, 128>>>(batch, fc_w, fc_b, out);
}

// round 4
// speedup vs baseline: 1.5141x; 1.5141x over previous
#include <cuda_runtime.h>
#include <cuda_bf16.h>
#include <math.h>

#define NN 50000
#define EE 800000
#define ET (EE + NN)
#define FIN 128
#define H1DIM 256
#define H2DIM 128
#define NGRAPH 64
#define NEG_SLOPE 0.2f

// ---------------- scratch ----------------------------------------------------
__device__ __align__(16) float g_h1[(size_t)NN * H1DIM];
__device__ __align__(16) float g_out1[(size_t)NN * H1DIM];
__device__ __align__(16) float g_h2[(size_t)NN * H2DIM];
__device__ __align__(16) float g_out2[(size_t)NN * H2DIM];
__device__ __align__(16) float g_es1[NN * 4];
__device__ __align__(16) float g_ed1[NN * 4];
__device__ __align__(16) float g_m1[NN * 4];   // per (dst,head) softmax max
__device__ __align__(16) float g_i1[NN * 4];   // per (dst,head) 1/sum
__device__ float g_es2[NN];
__device__ float g_ed2[NN];
__device__ float g_m2[NN];
__device__ float g_i2[NN];
__device__ int   g_cnt[NN];
__device__ int   g_off[NN + 1];
__device__ int   g_cur[NN];
__device__ int   g_esrc[ET];

// ---------------- CSR build --------------------------------------------------
__global__ void zero_counts_kernel() {
    int i = blockIdx.x * blockDim.x + threadIdx.x;
    if (i < NN) g_cnt[i] = 0;
}

__global__ void count_kernel(const int* __restrict__ ei) {
    int e = blockIdx.x * blockDim.x + threadIdx.x;
    if (e >= ET) return;
    int dst = (e < EE) ? ei[EE + e] : (e - EE);
    atomicAdd(&g_cnt[dst], 1);
}

__global__ void scan_kernel() {
    __shared__ int sdata[1024];
    __shared__ int s_carry;
    int tid = threadIdx.x;
    if (tid == 0) s_carry = 0;
    __syncthreads();
    for (int base = 0; base < NN; base += 1024) {
        int i = base + tid;
        int v = (i < NN) ? g_cnt[i] : 0;
        sdata[tid] = v;
        __syncthreads();
        #pragma unroll
        for (int d = 1; d < 1024; d <<= 1) {
            int t = (tid >= d) ? sdata[tid - d] : 0;
            __syncthreads();
            sdata[tid] += t;
            __syncthreads();
        }
        int carry = s_carry;
        if (i < NN) {
            g_off[i] = carry + sdata[tid] - v;
            g_cur[i] = carry + sdata[tid] - v;
        }
        __syncthreads();
        if (tid == 0) s_carry = carry + sdata[1023];
        __syncthreads();
    }
    if (tid == 0) g_off[NN] = s_carry;
}

__global__ void fill_kernel(const int* __restrict__ ei) {
    int e = blockIdx.x * blockDim.x + threadIdx.x;
    if (e >= ET) return;
    int src, dst;
    if (e < EE) { src = ei[e]; dst = ei[EE + e]; }
    else        { src = e - EE; dst = e - EE; }
    int pos = atomicAdd(&g_cur[dst], 1);
    g_esrc[pos] = src;
}

// ---------------- double-buffered GEMM: C[M,N] = A[M,K] @ B[K,N] -------------
#define BM 128
#define BN 128
#define BK 16

__device__ __forceinline__ float4 ldg4(const float* p) { return *(const float4*)p; }

__device__ __forceinline__ void gemm_body(
    const float* __restrict__ A, const float* __restrict__ B,
    float* __restrict__ C, int M, int N, int K)
{
    __shared__ float As[2][BK][BM];
    __shared__ float Bs[2][BK][BN];
    const int tid = threadIdx.x;
    const int bm = blockIdx.y * BM, bn = blockIdx.x * BN;
    const int tx = tid & 15, ty = tid >> 4;

    const int ar0 = tid >> 2,          ac0 = (tid & 3) * 4;
    const int ar1 = (tid + 256) >> 2,  ac1 = ((tid + 256) & 3) * 4;
    const int br0 = tid >> 5,          bc0 = (tid & 31) * 4;
    const int br1 = (tid + 256) >> 5,  bc1 = ((tid + 256) & 31) * 4;

    float acc[8][8];
    #pragma unroll
    for (int i = 0; i < 8; i++)
        #pragma unroll
        for (int j = 0; j < 8; j++) acc[i][j] = 0.f;

    float4 pa0, pa1, pb0, pb1;

    auto LDG = [&](int k0) {
        pa0 = (bm + ar0 < M) ? ldg4(A + (size_t)(bm + ar0) * K + k0 + ac0) : make_float4(0.f,0.f,0.f,0.f);
        pa1 = (bm + ar1 < M) ? ldg4(A + (size_t)(bm + ar1) * K + k0 + ac1) : make_float4(0.f,0.f,0.f,0.f);
        pb0 = ldg4(B + (size_t)(k0 + br0) * N + bn + bc0);
        pb1 = ldg4(B + (size_t)(k0 + br1) * N + bn + bc1);
    };
    auto STS = [&](int buf) {
        As[buf][ac0+0][ar0] = pa0.x; As[buf][ac0+1][ar0] = pa0.y;
        As[buf][ac0+2][ar0] = pa0.z; As[buf][ac0+3][ar0] = pa0.w;
        As[buf][ac1+0][ar1] = pa1.x; As[buf][ac1+1][ar1] = pa1.y;
        As[buf][ac1+2][ar1] = pa1.z; As[buf][ac1+3][ar1] = pa1.w;
        *(float4*)&Bs[buf][br0][bc0] = pb0;
        *(float4*)&Bs[buf][br1][bc1] = pb1;
    };

    LDG(0);
    STS(0);
    __syncthreads();

    const int T = K / BK;
    for (int t = 0; t < T; t++) {
        int cur = t & 1;
        if (t + 1 < T) LDG((t + 1) * BK);
        #pragma unroll
        for (int kk = 0; kk < BK; kk++) {
            float a[8], b[8];
            #pragma unroll
            for (int i = 0; i < 8; i++) a[i] = As[cur][kk][ty * 8 + i];
            #pragma unroll
            for (int j = 0; j < 8; j++) b[j] = Bs[cur][kk][tx * 8 + j];
            #pragma unroll
            for (int i = 0; i < 8; i++)
                #pragma unroll
                for (int j = 0; j < 8; j++)
                    acc[i][j] = fmaf(a[i], b[j], acc[i][j]);
        }
        if (t + 1 < T) { STS(cur ^ 1); __syncthreads(); }
    }

    #pragma unroll
    for (int i = 0; i < 8; i++) {
        int row = bm + ty * 8 + i;
        if (row >= M) continue;
        #pragma unroll
        for (int j = 0; j < 8; j += 4) {
            *(float4*)(C + (size_t)row * N + bn + tx * 8 + j) =
                make_float4(acc[i][j], acc[i][j+1], acc[i][j+2], acc[i][j+3]);
        }
    }
}

__global__ __launch_bounds__(256, 2) void gemm1_kernel(
    const float* __restrict__ x, const float* __restrict__ W1)
{
    gemm_body(x, W1, g_h1, NN, H1DIM, FIN);
}

__global__ __launch_bounds__(256, 2) void gemm2_kernel(
    const float* __restrict__ W2)
{
    gemm_body(g_out1, W2, g_h2, NN, H2DIM, H1DIM);
}

// ---------------- attention coefficients ------------------------------------
__global__ void coef1_kernel(const float* __restrict__ a_s, const float* __restrict__ a_d) {
    int idx = blockIdx.x * blockDim.x + threadIdx.x;
    if (idx >= NN * 4) return;
    int node = idx >> 2, head = idx & 3;
    const float* row = g_h1 + (size_t)node * H1DIM + head * 64;
    const float* as = a_s + head * 64;
    const float* ad = a_d + head * 64;
    float s = 0.f, d = 0.f;
    #pragma unroll 16
    for (int c = 0; c < 64; c++) {
        float h = row[c];
        s = fmaf(h, as[c], s);
        d = fmaf(h, ad[c], d);
    }
    g_es1[idx] = s;
    g_ed1[idx] = d;
}

__global__ void coef2_kernel(const float* __restrict__ a_s, const float* __restrict__ a_d) {
    int node = blockIdx.x * blockDim.x + threadIdx.x;
    if (node >= NN) return;
    const float* row = g_h2 + (size_t)node * H2DIM;
    float s = 0.f, d = 0.f;
    #pragma unroll 16
    for (int c = 0; c < 128; c++) {
        float h = row[c];
        s = fmaf(h, a_s[c], s);
        d = fmaf(h, a_d[c], d);
    }
    g_es2[node] = s;
    g_ed2[node] = d;
}

__device__ __forceinline__ float elu1(float x) {
    return x > 0.f ? x : expm1f(x);
}
__device__ __forceinline__ float lrelu(float x) {
    return x > 0.f ? x : NEG_SLOPE * x;
}

// ---------------- softmax stats: warp per dst, lane-parallel edges ----------
__global__ __launch_bounds__(256) void stats1_kernel() {
    int dst  = (blockIdx.x * blockDim.x + threadIdx.x) >> 5;
    int lane = threadIdx.x & 31;
    if (dst >= NN) return;
    int start = g_off[dst], end = g_off[dst + 1];
    float4 ed = *(const float4*)&g_ed1[dst * 4];
    float m0=-1e30f,m1=-1e30f,m2=-1e30f,m3=-1e30f;
    float s0=0.f,s1=0.f,s2=0.f,s3=0.f;
    for (int j = start + lane; j < end; j += 32) {
        int src = g_esrc[j];
        float4 es = *(const float4*)&g_es1[src * 4];
        float e0 = lrelu(es.x + ed.x), e1 = lrelu(es.y + ed.y);
        float e2 = lrelu(es.z + ed.z), e3 = lrelu(es.w + ed.w);
        float n0 = fmaxf(m0,e0); s0 = s0*__expf(m0-n0)+__expf(e0-n0); m0=n0;
        float n1 = fmaxf(m1,e1); s1 = s1*__expf(m1-n1)+__expf(e1-n1); m1=n1;
        float n2 = fmaxf(m2,e2); s2 = s2*__expf(m2-n2)+__expf(e2-n2); m2=n2;
        float n3 = fmaxf(m3,e3); s3 = s3*__expf(m3-n3)+__expf(e3-n3); m3=n3;
    }
    #pragma unroll
    for (int off = 16; off; off >>= 1) {
        float mo, so, n;
        mo = __shfl_xor_sync(0xffffffffu, m0, off); so = __shfl_xor_sync(0xffffffffu, s0, off);
        n = fmaxf(m0, mo); s0 = s0*__expf(m0-n) + so*__expf(mo-n); m0 = n;
        mo = __shfl_xor_sync(0xffffffffu, m1, off); so = __shfl_xor_sync(0xffffffffu, s1, off);
        n = fmaxf(m1, mo); s1 = s1*__expf(m1-n) + so*__expf(mo-n); m1 = n;
        mo = __shfl_xor_sync(0xffffffffu, m2, off); so = __shfl_xor_sync(0xffffffffu, s2, off);
        n = fmaxf(m2, mo); s2 = s2*__expf(m2-n) + so*__expf(mo-n); m2 = n;
        mo = __shfl_xor_sync(0xffffffffu, m3, off); so = __shfl_xor_sync(0xffffffffu, s3, off);
        n = fmaxf(m3, mo); s3 = s3*__expf(m3-n) + so*__expf(mo-n); m3 = n;
    }
    if (lane == 0) {
        *(float4*)&g_m1[dst * 4] = make_float4(m0, m1, m2, m3);
        *(float4*)&g_i1[dst * 4] = make_float4(1.f/s0, 1.f/s1, 1.f/s2, 1.f/s3);
    }
}

__global__ __launch_bounds__(256) void stats2_kernel() {
    int dst  = (blockIdx.x * blockDim.x + threadIdx.x) >> 5;
    int lane = threadIdx.x & 31;
    if (dst >= NN) return;
    int start = g_off[dst], end = g_off[dst + 1];
    float edv = g_ed2[dst];
    float m = -1e30f, s = 0.f;
    for (int j = start + lane; j < end; j += 32) {
        int src = g_esrc[j];
        float e = lrelu(g_es2[src] + edv);
        float n = fmaxf(m, e); s = s*__expf(m-n) + __expf(e-n); m = n;
    }
    #pragma unroll
    for (int off = 16; off; off >>= 1) {
        float mo = __shfl_xor_sync(0xffffffffu, m, off);
        float so = __shfl_xor_sync(0xffffffffu, s, off);
        float n = fmaxf(m, mo); s = s*__expf(m-n) + so*__expf(mo-n); m = n;
    }
    if (lane == 0) { g_m2[dst] = m; g_i2[dst] = 1.f / s; }
}

// ---------------- aggregation (pure weighted accumulate) ---------------------
__global__ __launch_bounds__(256) void agg1_kernel(const float* __restrict__ b1) {
    int w = (blockIdx.x * blockDim.x + threadIdx.x) >> 5;
    int lane = threadIdx.x & 31;
    if (w >= NN * 4) return;
    int dst = w >> 2, head = w & 3;
    int start = g_off[dst], end = g_off[dst + 1];
    float edv = g_ed1[dst * 4 + head];
    float m   = g_m1[dst * 4 + head];
    float inv = g_i1[dst * 4 + head];
    float acc0 = 0.f, acc1 = 0.f;
    for (int j = start; j < end; j++) {
        int src = g_esrc[j];
        float e = lrelu(g_es1[src * 4 + head] + edv);
        float wt = __expf(e - m) * inv;
        const float* hrow = g_h1 + (size_t)src * H1DIM + head * 64;
        acc0 = fmaf(wt, hrow[lane],      acc0);
        acc1 = fmaf(wt, hrow[lane + 32], acc1);
    }
    int o = head * 64 + lane;
    g_out1[(size_t)dst * H1DIM + o]      = elu1(acc0 + b1[o]);
    g_out1[(size_t)dst * H1DIM + o + 32] = elu1(acc1 + b1[o + 32]);
}

__global__ __launch_bounds__(256) void agg2_kernel(const float* __restrict__ b2) {
    int dst = (blockIdx.x * blockDim.x + threadIdx.x) >> 5;
    int lane = threadIdx.x & 31;
    if (dst >= NN) return;
    int start = g_off[dst], end = g_off[dst + 1];
    float edv = g_ed2[dst];
    float m   = g_m2[dst];
    float inv = g_i2[dst];
    float acc[4] = {0.f, 0.f, 0.f, 0.f};
    for (int j = start; j < end; j++) {
        int src = g_esrc[j];
        float e = lrelu(g_es2[src] + edv);
        float wt = __expf(e - m) * inv;
        const float* hrow = g_h2 + (size_t)src * H2DIM;
        #pragma unroll
        for (int r = 0; r < 4; r++)
            acc[r] = fmaf(wt, hrow[lane + 32 * r], acc[r]);
    }
    #pragma unroll
    for (int r = 0; r < 4; r++) {
        int o = lane + 32 * r;
        g_out2[(size_t)dst * H2DIM + o] = elu1(acc[r] + b2[o]);
    }
}

// ---------------- pooling + FC + log_softmax ---------------------------------
__device__ __forceinline__ int lb_i(const int* a, int n, int v) {
    int lo = 0, hi = n;
    while (lo < hi) { int mid = (lo + hi) >> 1; if (a[mid] < v) lo = mid + 1; else hi = mid; }
    return lo;
}

__global__ void pool_fc_kernel(const int* __restrict__ batch,
                               const float* __restrict__ fc_w,
                               const float* __restrict__ fc_b,
                               float* __restrict__ out)
{
    int g = blockIdx.x;
    int tid = threadIdx.x;
    __shared__ float sp[128];
    __shared__ float slog[10];
    int lo = lb_i(batch, NN, g);
    int hi = lb_i(batch, NN, g + 1);
    float s = 0.f;
    for (int i = lo; i < hi; i++) s += g_out2[(size_t)i * H2DIM + tid];
    float cnt = (float)(hi - lo);
    sp[tid] = s / fmaxf(cnt, 1.f);
    __syncthreads();
    if (tid < 10) {
        float l = fc_b[tid];
        #pragma unroll 16
        for (int c = 0; c < 128; c++) l = fmaf(sp[c], fc_w[c * 10 + tid], l);
        slog[tid] = l;
    }
    __syncthreads();
    if (tid == 0) {
        float mx = -1e30f;
        #pragma unroll
        for (int k = 0; k < 10; k++) mx = fmaxf(mx, slog[k]);
        float sum = 0.f;
        #pragma unroll
        for (int k = 0; k < 10; k++) sum += expf(slog[k] - mx);
        float lse = mx + logf(sum);
        #pragma unroll
        for (int k = 0; k < 10; k++) out[g * 10 + k] = slog[k] - lse;
    }
}

// ---------------- launch -----------------------------------------------------
extern "C" void kernel_launch(void* const* d_in, const int* in_sizes, int n_in,
                              void* d_out, int out_size)
{
    const float* x     = (const float*)d_in[0];
    const int*   ei    = (const int*)d_in[1];
    const int*   batch = (const int*)d_in[2];
    const float* W1    = (const float*)d_in[3];
    const float* a_s1  = (const float*)d_in[4];
    const float* a_d1  = (const float*)d_in[5];
    const float* b1    = (const float*)d_in[6];
    const float* W2    = (const float*)d_in[7];
    const float* a_s2  = (const float*)d_in[8];
    const float* a_d2  = (const float*)d_in[9];
    const float* b2    = (const float*)d_in[10];
    const float* fc_w  = (const float*)d_in[11];
    const float* fc_b  = (const float*)d_in[12];
    float* out = (float*)d_out;

    zero_counts_kernel<<<(NN + 255) / 256, 256>>>();
    count_kernel<<<(ET + 255) / 256, 256>>>(ei);
    scan_kernel<<<1, 1024>>>();
    fill_kernel<<<(ET + 255) / 256, 256>>>(ei);

    {
        dim3 grid(H1DIM / BN, (NN + BM - 1) / BM);
        gemm1_kernel<<<grid, 256>>>(x, W1);
    }
    coef1_kernel<<<(NN * 4 + 255) / 256, 256>>>(a_s1, a_d1);
    stats1_kernel<<<(NN * 32 + 255) / 256, 256>>>();
    agg1_kernel<<<(NN * 4 * 32 + 255) / 256, 256>>>(b1);

    {
        dim3 grid(H2DIM / BN, (NN + BM - 1) / BM);
        gemm2_kernel<<<grid, 256>>>(W2);
    }
    coef2_kernel<<<(NN + 255) / 256, 256>>>(a_s2, a_d2);
    stats2_kernel<<<(NN * 32 + 255) / 256, 256>>>();
    agg2_kernel<<<(NN * 32 + 255) / 256, 256>>>(b2);

    pool_fc_kernel<<<NGRAPH, 128>>>(batch, fc_w, fc_b, out);
}

// round 6
// speedup vs baseline: 1.9427x; 1.2831x over previous
#include <cuda_runtime.h>
#include <cuda_bf16.h>
#include <math.h>
#include <stdint.h>

#define NN 50000
#define EE 800000
#define ET (EE + NN)
#define FIN 128
#define H1DIM 256
#define H2DIM 128
#define NGRAPH 64
#define NEG_SLOPE 0.2f
#define NBLK 49   // ceil(NN/1024)

// ---------------- scratch ----------------------------------------------------
__device__ __align__(16) float g_h1[(size_t)NN * H1DIM];
__device__ __align__(16) float g_out1[(size_t)NN * H1DIM];
__device__ __align__(16) float g_h2[(size_t)NN * H2DIM];
__device__ __align__(16) float g_out2[(size_t)NN * H2DIM];
__device__ __align__(16) float g_es1[NN * 4];
__device__ __align__(16) float g_ed1[NN * 4];
__device__ __align__(16) float g_m1[NN * 4];
__device__ __align__(16) float g_i1[NN * 4];
__device__ float g_es2[NN];
__device__ float g_ed2[NN];
__device__ float g_m2[NN];
__device__ float g_i2[NN];
__device__ int   g_cnt[NN];
__device__ int   g_off[NN + 1];
__device__ int   g_cur[NN];
__device__ int   g_esrc[ET];
__device__ int   g_bsum[NBLK];
__device__ int   g_boff[NBLK];

// ---------------- CSR build --------------------------------------------------
__global__ void zero_counts_kernel() {
    int i = blockIdx.x * blockDim.x + threadIdx.x;
    if (i < NN) g_cnt[i] = 0;
}

__global__ void count_kernel(const int* __restrict__ ei) {
    int e = blockIdx.x * blockDim.x + threadIdx.x;
    if (e >= ET) return;
    int dst = (e < EE) ? ei[EE + e] : (e - EE);
    atomicAdd(&g_cnt[dst], 1);
}

__global__ void scan1_kernel() {
    __shared__ int sdata[1024];
    int b = blockIdx.x, tid = threadIdx.x;
    int i = b * 1024 + tid;
    int v = (i < NN) ? g_cnt[i] : 0;
    sdata[tid] = v;
    __syncthreads();
    #pragma unroll
    for (int d = 1; d < 1024; d <<= 1) {
        int t = (tid >= d) ? sdata[tid - d] : 0;
        __syncthreads();
        sdata[tid] += t;
        __syncthreads();
    }
    if (i < NN) g_off[i] = sdata[tid] - v;   // local exclusive
    if (tid == 1023) g_bsum[b] = sdata[1023];
}

__global__ void scan2_kernel() {
    int acc = 0;
    for (int k = 0; k < NBLK; k++) { g_boff[k] = acc; acc += g_bsum[k]; }
    g_off[NN] = acc;
}

__global__ void scan3_kernel() {
    int i = blockIdx.x * blockDim.x + threadIdx.x;
    if (i >= NN) return;
    int v = g_off[i] + g_boff[i >> 10];
    g_off[i] = v;
    g_cur[i] = v;
}

__global__ void fill_kernel(const int* __restrict__ ei) {
    int e = blockIdx.x * blockDim.x + threadIdx.x;
    if (e >= ET) return;
    int src, dst;
    if (e < EE) { src = ei[e]; dst = ei[EE + e]; }
    else        { src = e - EE; dst = e - EE; }
    int pos = atomicAdd(&g_cur[dst], 1);
    g_esrc[pos] = src;
}

// ---------------- TF32 tensor-core GEMM (3-pass fp32-accurate) ---------------
#define BM 128
#define BN 128
#define BK 16
#define PADK 8     // row pad so fragment LDS is bank-conflict-free

__device__ __forceinline__ float4 ldg4(const float* p) { return *(const float4*)p; }

__device__ __forceinline__ uint32_t f2tf(float x) {
    uint32_t u;
    asm("cvt.rna.tf32.f32 %0, %1;" : "=r"(u) : "f"(x));
    return u;
}

__device__ __forceinline__ void mma8(float* c, const uint32_t* a, const uint32_t* b) {
    asm volatile(
        "mma.sync.aligned.m16n8k8.row.col.f32.tf32.tf32.f32 "
        "{%0,%1,%2,%3},{%4,%5,%6,%7},{%8,%9},{%0,%1,%2,%3};"
        : "+f"(c[0]), "+f"(c[1]), "+f"(c[2]), "+f"(c[3])
        : "r"(a[0]), "r"(a[1]), "r"(a[2]), "r"(a[3]), "r"(b[0]), "r"(b[1]));
}

__device__ __forceinline__ void gemm_body(
    const float* __restrict__ A, const float* __restrict__ B,
    float* __restrict__ C, int M, int N, int K)
{
    __shared__ float As[2][BK][BM + PADK];
    __shared__ float Bs[2][BK][BN + PADK];
    const int tid  = threadIdx.x;
    const int lane = tid & 31;
    const int wid  = tid >> 5;
    const int warp_m = wid >> 2;      // 0..1 -> 64 rows each
    const int warp_n = wid & 3;       // 0..3 -> 32 cols each
    const int bm = blockIdx.y * BM, bn = blockIdx.x * BN;
    const int tg = lane & 3;          // k sub-index
    const int tr = lane >> 2;         // row/col sub-index

    const int ar0 = tid >> 2, ac0 = (tid & 3) * 4, ar1 = ar0 + 64;
    const int br0 = tid >> 5, bc0 = (tid & 31) * 4, br1 = br0 + 8;

    float c[4][4][4];
    #pragma unroll
    for (int mt = 0; mt < 4; mt++)
        #pragma unroll
        for (int nt = 0; nt < 4; nt++)
            #pragma unroll
            for (int r = 0; r < 4; r++) c[mt][nt][r] = 0.f;

    float4 pa0, pa1, pb0, pb1;
    auto LDG = [&](int k0) {
        pa0 = (bm + ar0 < M) ? ldg4(A + (size_t)(bm + ar0) * K + k0 + ac0) : make_float4(0.f,0.f,0.f,0.f);
        pa1 = (bm + ar1 < M) ? ldg4(A + (size_t)(bm + ar1) * K + k0 + ac0) : make_float4(0.f,0.f,0.f,0.f);
        pb0 = ldg4(B + (size_t)(k0 + br0) * N + bn + bc0);
        pb1 = ldg4(B + (size_t)(k0 + br1) * N + bn + bc0);
    };
    auto STS = [&](int buf) {
        As[buf][ac0+0][ar0] = pa0.x; As[buf][ac0+1][ar0] = pa0.y;
        As[buf][ac0+2][ar0] = pa0.z; As[buf][ac0+3][ar0] = pa0.w;
        As[buf][ac0+0][ar1] = pa1.x; As[buf][ac0+1][ar1] = pa1.y;
        As[buf][ac0+2][ar1] = pa1.z; As[buf][ac0+3][ar1] = pa1.w;
        *(float4*)&Bs[buf][br0][bc0] = pb0;
        *(float4*)&Bs[buf][br1][bc0] = pb1;
    };

    LDG(0);
    STS(0);
    __syncthreads();

    const int T = K / BK;
    for (int t = 0; t < T; t++) {
        int cur = t & 1;
        if (t + 1 < T) LDG((t + 1) * BK);
        #pragma unroll
        for (int ks = 0; ks < 2; ks++) {
            const int kk = ks * 8;
            uint32_t ahi[4][4], alo[4][4], bhi[4][2], blo[4][2];
            #pragma unroll
            for (int mt = 0; mt < 4; mt++) {
                int mb = warp_m * 64 + mt * 16;
                float a0 = As[cur][kk + tg    ][mb + tr];
                float a1 = As[cur][kk + tg    ][mb + tr + 8];
                float a2 = As[cur][kk + tg + 4][mb + tr];
                float a3 = As[cur][kk + tg + 4][mb + tr + 8];
                ahi[mt][0] = f2tf(a0); alo[mt][0] = f2tf(a0 - __uint_as_float(ahi[mt][0]));
                ahi[mt][1] = f2tf(a1); alo[mt][1] = f2tf(a1 - __uint_as_float(ahi[mt][1]));
                ahi[mt][2] = f2tf(a2); alo[mt][2] = f2tf(a2 - __uint_as_float(ahi[mt][2]));
                ahi[mt][3] = f2tf(a3); alo[mt][3] = f2tf(a3 - __uint_as_float(ahi[mt][3]));
            }
            #pragma unroll
            for (int nt = 0; nt < 4; nt++) {
                int nb = warp_n * 32 + nt * 8;
                float b0 = Bs[cur][kk + tg    ][nb + tr];
                float b1 = Bs[cur][kk + tg + 4][nb + tr];
                bhi[nt][0] = f2tf(b0); blo[nt][0] = f2tf(b0 - __uint_as_float(bhi[nt][0]));
                bhi[nt][1] = f2tf(b1); blo[nt][1] = f2tf(b1 - __uint_as_float(bhi[nt][1]));
            }
            #pragma unroll
            for (int mt = 0; mt < 4; mt++)
                #pragma unroll
                for (int nt = 0; nt < 4; nt++) {
                    mma8(c[mt][nt], ahi[mt], bhi[nt]);
                    mma8(c[mt][nt], alo[mt], bhi[nt]);
                    mma8(c[mt][nt], ahi[mt], blo[nt]);
                }
        }
        if (t + 1 < T) { STS(cur ^ 1); __syncthreads(); }
    }

    // epilogue
    #pragma unroll
    for (int mt = 0; mt < 4; mt++) {
        int row0 = bm + warp_m * 64 + mt * 16 + tr;
        int row1 = row0 + 8;
        #pragma unroll
        for (int nt = 0; nt < 4; nt++) {
            int col = bn + warp_n * 32 + nt * 8 + tg * 2;
            if (row0 < M) *(float2*)(C + (size_t)row0 * N + col) = make_float2(c[mt][nt][0], c[mt][nt][1]);
            if (row1 < M) *(float2*)(C + (size_t)row1 * N + col) = make_float2(c[mt][nt][2], c[mt][nt][3]);
        }
    }
}

__global__ __launch_bounds__(256) void gemm1_kernel(
    const float* __restrict__ x, const float* __restrict__ W1)
{
    gemm_body(x, W1, g_h1, NN, H1DIM, FIN);
}

__global__ __launch_bounds__(256) void gemm2_kernel(
    const float* __restrict__ W2)
{
    gemm_body(g_out1, W2, g_h2, NN, H2DIM, H1DIM);
}

// ---------------- attention coefficients ------------------------------------
__global__ void coef1_kernel(const float* __restrict__ a_s, const float* __restrict__ a_d) {
    int idx = blockIdx.x * blockDim.x + threadIdx.x;
    if (idx >= NN * 4) return;
    int node = idx >> 2, head = idx & 3;
    const float* row = g_h1 + (size_t)node * H1DIM + head * 64;
    const float* as = a_s + head * 64;
    const float* ad = a_d + head * 64;
    float s = 0.f, d = 0.f;
    #pragma unroll 16
    for (int c = 0; c < 64; c++) {
        float h = row[c];
        s = fmaf(h, as[c], s);
        d = fmaf(h, ad[c], d);
    }
    g_es1[idx] = s;
    g_ed1[idx] = d;
}

__global__ void coef2_kernel(const float* __restrict__ a_s, const float* __restrict__ a_d) {
    int node = blockIdx.x * blockDim.x + threadIdx.x;
    if (node >= NN) return;
    const float* row = g_h2 + (size_t)node * H2DIM;
    float s = 0.f, d = 0.f;
    #pragma unroll 16
    for (int c = 0; c < 128; c++) {
        float h = row[c];
        s = fmaf(h, a_s[c], s);
        d = fmaf(h, a_d[c], d);
    }
    g_es2[node] = s;
    g_ed2[node] = d;
}

__device__ __forceinline__ float elu1(float x)  { return x > 0.f ? x : expm1f(x); }
__device__ __forceinline__ float lrelu(float x) { return x > 0.f ? x : NEG_SLOPE * x; }

// ---------------- softmax stats ----------------------------------------------
__global__ __launch_bounds__(256) void stats1_kernel() {
    int dst  = (blockIdx.x * blockDim.x + threadIdx.x) >> 5;
    int lane = threadIdx.x & 31;
    if (dst >= NN) return;
    int start = g_off[dst], end = g_off[dst + 1];
    float4 ed = *(const float4*)&g_ed1[dst * 4];
    float m0=-1e30f,m1=-1e30f,m2=-1e30f,m3=-1e30f;
    float s0=0.f,s1=0.f,s2=0.f,s3=0.f;
    for (int j = start + lane; j < end; j += 32) {
        int src = g_esrc[j];
        float4 es = *(const float4*)&g_es1[src * 4];
        float e0 = lrelu(es.x + ed.x), e1 = lrelu(es.y + ed.y);
        float e2 = lrelu(es.z + ed.z), e3 = lrelu(es.w + ed.w);
        float n0 = fmaxf(m0,e0); s0 = s0*__expf(m0-n0)+__expf(e0-n0); m0=n0;
        float n1 = fmaxf(m1,e1); s1 = s1*__expf(m1-n1)+__expf(e1-n1); m1=n1;
        float n2 = fmaxf(m2,e2); s2 = s2*__expf(m2-n2)+__expf(e2-n2); m2=n2;
        float n3 = fmaxf(m3,e3); s3 = s3*__expf(m3-n3)+__expf(e3-n3); m3=n3;
    }
    #pragma unroll
    for (int off = 16; off; off >>= 1) {
        float mo, so, n;
        mo = __shfl_xor_sync(0xffffffffu, m0, off); so = __shfl_xor_sync(0xffffffffu, s0, off);
        n = fmaxf(m0, mo); s0 = s0*__expf(m0-n) + so*__expf(mo-n); m0 = n;
        mo = __shfl_xor_sync(0xffffffffu, m1, off); so = __shfl_xor_sync(0xffffffffu, s1, off);
        n = fmaxf(m1, mo); s1 = s1*__expf(m1-n) + so*__expf(mo-n); m1 = n;
        mo = __shfl_xor_sync(0xffffffffu, m2, off); so = __shfl_xor_sync(0xffffffffu, s2, off);
        n = fmaxf(m2, mo); s2 = s2*__expf(m2-n) + so*__expf(mo-n); m2 = n;
        mo = __shfl_xor_sync(0xffffffffu, m3, off); so = __shfl_xor_sync(0xffffffffu, s3, off);
        n = fmaxf(m3, mo); s3 = s3*__expf(m3-n) + so*__expf(mo-n); m3 = n;
    }
    if (lane == 0) {
        *(float4*)&g_m1[dst * 4] = make_float4(m0, m1, m2, m3);
        *(float4*)&g_i1[dst * 4] = make_float4(1.f/s0, 1.f/s1, 1.f/s2, 1.f/s3);
    }
}

__global__ __launch_bounds__(256) void stats2_kernel() {
    int dst  = (blockIdx.x * blockDim.x + threadIdx.x) >> 5;
    int lane = threadIdx.x & 31;
    if (dst >= NN) return;
    int start = g_off[dst], end = g_off[dst + 1];
    float edv = g_ed2[dst];
    float m = -1e30f, s = 0.f;
    for (int j = start + lane; j < end; j += 32) {
        int src = g_esrc[j];
        float e = lrelu(g_es2[src] + edv);
        float n = fmaxf(m, e); s = s*__expf(m-n) + __expf(e-n); m = n;
    }
    #pragma unroll
    for (int off = 16; off; off >>= 1) {
        float mo = __shfl_xor_sync(0xffffffffu, m, off);
        float so = __shfl_xor_sync(0xffffffffu, s, off);
        float n = fmaxf(m, mo); s = s*__expf(m-n) + so*__expf(mo-n); m = n;
    }
    if (lane == 0) { g_m2[dst] = m; g_i2[dst] = 1.f / s; }
}

// ---------------- aggregation ------------------------------------------------
__global__ __launch_bounds__(256) void agg1_kernel(const float* __restrict__ b1) {
    int w = (blockIdx.x * blockDim.x + threadIdx.x) >> 5;
    int lane = threadIdx.x & 31;
    if (w >= NN * 4) return;
    int dst = w >> 2, head = w & 3;
    int start = g_off[dst], end = g_off[dst + 1];
    float edv = g_ed1[dst * 4 + head];
    float m   = g_m1[dst * 4 + head];
    float inv = g_i1[dst * 4 + head];
    float acc0 = 0.f, acc1 = 0.f;
    for (int j = start; j < end; j++) {
        int src = g_esrc[j];
        float e = lrelu(g_es1[src * 4 + head] + edv);
        float wt = __expf(e - m) * inv;
        const float* hrow = g_h1 + (size_t)src * H1DIM + head * 64;
        acc0 = fmaf(wt, hrow[lane],      acc0);
        acc1 = fmaf(wt, hrow[lane + 32], acc1);
    }
    int o = head * 64 + lane;
    g_out1[(size_t)dst * H1DIM + o]      = elu1(acc0 + b1[o]);
    g_out1[(size_t)dst * H1DIM + o + 32] = elu1(acc1 + b1[o + 32]);
}

__global__ __launch_bounds__(256) void agg2_kernel(const float* __restrict__ b2) {
    int dst = (blockIdx.x * blockDim.x + threadIdx.x) >> 5;
    int lane = threadIdx.x & 31;
    if (dst >= NN) return;
    int start = g_off[dst], end = g_off[dst + 1];
    float edv = g_ed2[dst];
    float m   = g_m2[dst];
    float inv = g_i2[dst];
    float acc[4] = {0.f, 0.f, 0.f, 0.f};
    for (int j = start; j < end; j++) {
        int src = g_esrc[j];
        float e = lrelu(g_es2[src] + edv);
        float wt = __expf(e - m) * inv;
        const float* hrow = g_h2 + (size_t)src * H2DIM;
        #pragma unroll
        for (int r = 0; r < 4; r++)
            acc[r] = fmaf(wt, hrow[lane + 32 * r], acc[r]);
    }
    #pragma unroll
    for (int r = 0; r < 4; r++) {
        int o = lane + 32 * r;
        g_out2[(size_t)dst * H2DIM + o] = elu1(acc[r] + b2[o]);
    }
}

// ---------------- pooling + FC + log_softmax ---------------------------------
__device__ __forceinline__ int lb_i(const int* a, int n, int v) {
    int lo = 0, hi = n;
    while (lo < hi) { int mid = (lo + hi) >> 1; if (a[mid] < v) lo = mid + 1; else hi = mid; }
    return lo;
}

__global__ void pool_fc_kernel(const int* __restrict__ batch,
                               const float* __restrict__ fc_w,
                               const float* __restrict__ fc_b,
                               float* __restrict__ out)
{
    int g = blockIdx.x;
    int tid = threadIdx.x;
    __shared__ float sp[128];
    __shared__ float slog[10];
    int lo = lb_i(batch, NN, g);
    int hi = lb_i(batch, NN, g + 1);
    float s = 0.f;
    for (int i = lo; i < hi; i++) s += g_out2[(size_t)i * H2DIM + tid];
    float cnt = (float)(hi - lo);
    sp[tid] = s / fmaxf(cnt, 1.f);
    __syncthreads();
    if (tid < 10) {
        float l = fc_b[tid];
        #pragma unroll 16
        for (int c = 0; c < 128; c++) l = fmaf(sp[c], fc_w[c * 10 + tid], l);
        slog[tid] = l;
    }
    __syncthreads();
    if (tid == 0) {
        float mx = -1e30f;
        #pragma unroll
        for (int k = 0; k < 10; k++) mx = fmaxf(mx, slog[k]);
        float sum = 0.f;
        #pragma unroll
        for (int k = 0; k < 10; k++) sum += expf(slog[k] - mx);
        float lse = mx + logf(sum);
        #pragma unroll
        for (int k = 0; k < 10; k++) out[g * 10 + k] = slog[k] - lse;
    }
}

// ---------------- launch -----------------------------------------------------
extern "C" void kernel_launch(void* const* d_in, const int* in_sizes, int n_in,
                              void* d_out, int out_size)
{
    const float* x     = (const float*)d_in[0];
    const int*   ei    = (const int*)d_in[1];
    const int*   batch = (const int*)d_in[2];
    const float* W1    = (const float*)d_in[3];
    const float* a_s1  = (const float*)d_in[4];
    const float* a_d1  = (const float*)d_in[5];
    const float* b1    = (const float*)d_in[6];
    const float* W2    = (const float*)d_in[7];
    const float* a_s2  = (const float*)d_in[8];
    const float* a_d2  = (const float*)d_in[9];
    const float* b2    = (const float*)d_in[10];
    const float* fc_w  = (const float*)d_in[11];
    const float* fc_b  = (const float*)d_in[12];
    float* out = (float*)d_out;

    zero_counts_kernel<<<(NN + 255) / 256, 256>>>();
    count_kernel<<<(ET + 255) / 256, 256>>>(ei);
    scan1_kernel<<<NBLK, 1024>>>();
    scan2_kernel<<<1, 1>>>();
    scan3_kernel<<<(NN + 255) / 256, 256>>>();
    fill_kernel<<<(ET + 255) / 256, 256>>>(ei);

    {
        dim3 grid(H1DIM / BN, (NN + BM - 1) / BM);
        gemm1_kernel<<<grid, 256>>>(x, W1);
    }
    coef1_kernel<<<(NN * 4 + 255) / 256, 256>>>(a_s1, a_d1);
    stats1_kernel<<<(NN * 32 + 255) / 256, 256>>>();
    agg1_kernel<<<(NN * 4 * 32 + 255) / 256, 256>>>(b1);

    {
        dim3 grid(H2DIM / BN, (NN + BM - 1) / BM);
        gemm2_kernel<<<grid, 256>>>(W2);
    }
    coef2_kernel<<<(NN + 255) / 256, 256>>>(a_s2, a_d2);
    stats2_kernel<<<(NN * 32 + 255) / 256, 256>>>();
    agg2_kernel<<<(NN * 32 + 255) / 256, 256>>>(b2);

    pool_fc_kernel<<<NGRAPH, 128>>>(batch, fc_w, fc_b, out);
}

// round 7
// speedup vs baseline: 2.2130x; 1.1392x over previous
#include <cuda_runtime.h>
#include <cuda_bf16.h>
#include <math.h>
#include <stdint.h>

#define NN 50000
#define EE 800000
#define ET (EE + NN)
#define FIN 128
#define H1DIM 256
#define H2DIM 128
#define NGRAPH 64
#define NEG_SLOPE 0.2f
#define NBLK 49   // ceil(NN/1024)

// ---------------- scratch ----------------------------------------------------
__device__ __align__(16) float g_h1[(size_t)NN * H1DIM];
__device__ __align__(16) float g_out1[(size_t)NN * H1DIM];
__device__ __align__(16) float g_h2[(size_t)NN * H2DIM];
__device__ __align__(16) float g_out2[(size_t)NN * H2DIM];
__device__ __align__(16) float g_es1[NN * 4];
__device__ __align__(16) float g_ed1[NN * 4];
__device__ __align__(16) float g_m1[NN * 4];
__device__ __align__(16) float g_i1[NN * 4];
__device__ float g_es2[NN];
__device__ float g_ed2[NN];
__device__ float g_m2[NN];
__device__ float g_i2[NN];
__device__ int   g_cnt[NN];
__device__ int   g_off[NN + 1];
__device__ int   g_cur[NN];
__device__ int   g_esrc[ET];
__device__ int   g_bsum[NBLK];
__device__ int   g_boff[NBLK];

// ---------------- CSR build --------------------------------------------------
__global__ void zero_counts_kernel() {
    int i = blockIdx.x * blockDim.x + threadIdx.x;
    if (i < NN) g_cnt[i] = 0;
}

__global__ void count_kernel(const int* __restrict__ ei) {
    int e = blockIdx.x * blockDim.x + threadIdx.x;
    if (e >= ET) return;
    int dst = (e < EE) ? ei[EE + e] : (e - EE);
    atomicAdd(&g_cnt[dst], 1);
}

__global__ void scan1_kernel() {
    __shared__ int sdata[1024];
    int b = blockIdx.x, tid = threadIdx.x;
    int i = b * 1024 + tid;
    int v = (i < NN) ? g_cnt[i] : 0;
    sdata[tid] = v;
    __syncthreads();
    #pragma unroll
    for (int d = 1; d < 1024; d <<= 1) {
        int t = (tid >= d) ? sdata[tid - d] : 0;
        __syncthreads();
        sdata[tid] += t;
        __syncthreads();
    }
    if (i < NN) g_off[i] = sdata[tid] - v;   // local exclusive
    if (tid == 1023) g_bsum[b] = sdata[1023];
}

__global__ void scan2_kernel() {
    int t = threadIdx.x;            // 64 threads
    int lane = t & 31, w = t >> 5;
    int v = (t < NBLK) ? g_bsum[t] : 0;
    int x = v;
    #pragma unroll
    for (int d = 1; d < 32; d <<= 1) {
        int y = __shfl_up_sync(0xffffffffu, x, d);
        if (lane >= d) x += y;
    }
    __shared__ int wt[2];
    if (lane == 31) wt[w] = x;
    __syncthreads();
    if (w == 1) x += wt[0];
    if (t < NBLK) g_boff[t] = x - v;   // exclusive
}

__global__ void scan3_kernel() {
    int i = blockIdx.x * blockDim.x + threadIdx.x;
    if (i >= NN) return;
    int v = g_off[i] + g_boff[i >> 10];
    g_off[i] = v;
    g_cur[i] = v;
    if (i == 0) g_off[NN] = ET;
}

__global__ void fill_kernel(const int* __restrict__ ei) {
    int e = blockIdx.x * blockDim.x + threadIdx.x;
    if (e >= ET) return;
    int src, dst;
    if (e < EE) { src = ei[e]; dst = ei[EE + e]; }
    else        { src = e - EE; dst = e - EE; }
    int pos = atomicAdd(&g_cur[dst], 1);
    g_esrc[pos] = src;
}

// ---------------- TF32 tensor-core GEMM, pre-split hi/lo in SMEM -------------
#define BM 128
#define BN 128
#define BK 8
#define PADK 8

__device__ __forceinline__ float4 ldg4(const float* p) { return *(const float4*)p; }

__device__ __forceinline__ uint32_t f2tf(float x) {
    uint32_t u;
    asm("cvt.rna.tf32.f32 %0, %1;" : "=r"(u) : "f"(x));
    return u;
}

__device__ __forceinline__ void mma8(float* c, const uint32_t* a, const uint32_t* b) {
    asm volatile(
        "mma.sync.aligned.m16n8k8.row.col.f32.tf32.tf32.f32 "
        "{%0,%1,%2,%3},{%4,%5,%6,%7},{%8,%9},{%0,%1,%2,%3};"
        : "+f"(c[0]), "+f"(c[1]), "+f"(c[2]), "+f"(c[3])
        : "r"(a[0]), "r"(a[1]), "r"(a[2]), "r"(a[3]), "r"(b[0]), "r"(b[1]));
}

__device__ __forceinline__ void gemm_body(
    const float* __restrict__ A, const float* __restrict__ B,
    float* __restrict__ C, int M, int N, int K)
{
    __shared__ uint32_t Ahi[2][BK][BM + PADK];
    __shared__ uint32_t Alo[2][BK][BM + PADK];
    __shared__ uint32_t Bhi[2][BK][BN + PADK];
    __shared__ uint32_t Blo[2][BK][BN + PADK];

    const int tid  = threadIdx.x;
    const int lane = tid & 31;
    const int wid  = tid >> 5;
    const int warp_m = wid >> 2;      // 0..1 -> 64 rows each
    const int warp_n = wid & 3;       // 0..3 -> 32 cols each
    const int bm = blockIdx.y * BM, bn = blockIdx.x * BN;
    const int tg = lane & 3;          // k sub-index
    const int tr = lane >> 2;         // row/col sub-index

    // A loader: rows contiguous in tid (conflict-free scalar STS)
    const int ar = tid & 127, ac = (tid >> 7) * 4;
    // B loader: vector STS
    const int br = tid >> 5, bc = (tid & 31) * 4;

    float c[4][4][4];
    #pragma unroll
    for (int mt = 0; mt < 4; mt++)
        #pragma unroll
        for (int nt = 0; nt < 4; nt++)
            #pragma unroll
            for (int r = 0; r < 4; r++) c[mt][nt][r] = 0.f;

    float4 pa, pb;
    auto LDG = [&](int k0) {
        pa = (bm + ar < M) ? ldg4(A + (size_t)(bm + ar) * K + k0 + ac) : make_float4(0.f,0.f,0.f,0.f);
        pb = ldg4(B + (size_t)(k0 + br) * N + bn + bc);
    };
    auto STS = [&](int buf) {
        float av[4] = {pa.x, pa.y, pa.z, pa.w};
        #pragma unroll
        for (int i = 0; i < 4; i++) {
            uint32_t hi = f2tf(av[i]);
            uint32_t lo = f2tf(av[i] - __uint_as_float(hi));
            Ahi[buf][ac + i][ar] = hi;
            Alo[buf][ac + i][ar] = lo;
        }
        float bv[4] = {pb.x, pb.y, pb.z, pb.w};
        uint4 vh, vl;
        uint32_t h0 = f2tf(bv[0]), h1 = f2tf(bv[1]), h2 = f2tf(bv[2]), h3 = f2tf(bv[3]);
        vh = make_uint4(h0, h1, h2, h3);
        vl = make_uint4(f2tf(bv[0] - __uint_as_float(h0)),
                        f2tf(bv[1] - __uint_as_float(h1)),
                        f2tf(bv[2] - __uint_as_float(h2)),
                        f2tf(bv[3] - __uint_as_float(h3)));
        *(uint4*)&Bhi[buf][br][bc] = vh;
        *(uint4*)&Blo[buf][br][bc] = vl;
    };

    LDG(0);
    STS(0);
    __syncthreads();

    const int T = K / BK;
    for (int t = 0; t < T; t++) {
        int cur = t & 1;
        if (t + 1 < T) LDG((t + 1) * BK);

        uint32_t ahi[4][4], alo[4][4], bhi[4][2], blo[4][2];
        #pragma unroll
        for (int mt = 0; mt < 4; mt++) {
            int mb = warp_m * 64 + mt * 16;
            ahi[mt][0] = Ahi[cur][tg    ][mb + tr];
            ahi[mt][1] = Ahi[cur][tg    ][mb + tr + 8];
            ahi[mt][2] = Ahi[cur][tg + 4][mb + tr];
            ahi[mt][3] = Ahi[cur][tg + 4][mb + tr + 8];
            alo[mt][0] = Alo[cur][tg    ][mb + tr];
            alo[mt][1] = Alo[cur][tg    ][mb + tr + 8];
            alo[mt][2] = Alo[cur][tg + 4][mb + tr];
            alo[mt][3] = Alo[cur][tg + 4][mb + tr + 8];
        }
        #pragma unroll
        for (int nt = 0; nt < 4; nt++) {
            int nb = warp_n * 32 + nt * 8;
            bhi[nt][0] = Bhi[cur][tg    ][nb + tr];
            bhi[nt][1] = Bhi[cur][tg + 4][nb + tr];
            blo[nt][0] = Blo[cur][tg    ][nb + tr];
            blo[nt][1] = Blo[cur][tg + 4][nb + tr];
        }
        #pragma unroll
        for (int mt = 0; mt < 4; mt++)
            #pragma unroll
            for (int nt = 0; nt < 4; nt++) {
                mma8(c[mt][nt], ahi[mt], bhi[nt]);
                mma8(c[mt][nt], alo[mt], bhi[nt]);
                mma8(c[mt][nt], ahi[mt], blo[nt]);
            }

        if (t + 1 < T) { STS(cur ^ 1); __syncthreads(); }
    }

    #pragma unroll
    for (int mt = 0; mt < 4; mt++) {
        int row0 = bm + warp_m * 64 + mt * 16 + tr;
        int row1 = row0 + 8;
        #pragma unroll
        for (int nt = 0; nt < 4; nt++) {
            int col = bn + warp_n * 32 + nt * 8 + tg * 2;
            if (row0 < M) *(float2*)(C + (size_t)row0 * N + col) = make_float2(c[mt][nt][0], c[mt][nt][1]);
            if (row1 < M) *(float2*)(C + (size_t)row1 * N + col) = make_float2(c[mt][nt][2], c[mt][nt][3]);
        }
    }
}

__global__ __launch_bounds__(256) void gemm1_kernel(
    const float* __restrict__ x, const float* __restrict__ W1)
{
    gemm_body(x, W1, g_h1, NN, H1DIM, FIN);
}

__global__ __launch_bounds__(256) void gemm2_kernel(
    const float* __restrict__ W2)
{
    gemm_body(g_out1, W2, g_h2, NN, H2DIM, H1DIM);
}

// ---------------- attention coefficients ------------------------------------
__global__ void coef1_kernel(const float* __restrict__ a_s, const float* __restrict__ a_d) {
    int idx = blockIdx.x * blockDim.x + threadIdx.x;
    if (idx >= NN * 4) return;
    int node = idx >> 2, head = idx & 3;
    const float* row = g_h1 + (size_t)node * H1DIM + head * 64;
    const float* as = a_s + head * 64;
    const float* ad = a_d + head * 64;
    float s = 0.f, d = 0.f;
    #pragma unroll 16
    for (int c = 0; c < 64; c++) {
        float h = row[c];
        s = fmaf(h, as[c], s);
        d = fmaf(h, ad[c], d);
    }
    g_es1[idx] = s;
    g_ed1[idx] = d;
}

__global__ void coef2_kernel(const float* __restrict__ a_s, const float* __restrict__ a_d) {
    int node = blockIdx.x * blockDim.x + threadIdx.x;
    if (node >= NN) return;
    const float* row = g_h2 + (size_t)node * H2DIM;
    float s = 0.f, d = 0.f;
    #pragma unroll 16
    for (int c = 0; c < 128; c++) {
        float h = row[c];
        s = fmaf(h, a_s[c], s);
        d = fmaf(h, a_d[c], d);
    }
    g_es2[node] = s;
    g_ed2[node] = d;
}

__device__ __forceinline__ float elu1(float x)  { return x > 0.f ? x : expm1f(x); }
__device__ __forceinline__ float lrelu(float x) { return x > 0.f ? x : NEG_SLOPE * x; }

// ---------------- softmax stats ----------------------------------------------
__global__ __launch_bounds__(256) void stats1_kernel() {
    int dst  = (blockIdx.x * blockDim.x + threadIdx.x) >> 5;
    int lane = threadIdx.x & 31;
    if (dst >= NN) return;
    int start = g_off[dst], end = g_off[dst + 1];
    float4 ed = *(const float4*)&g_ed1[dst * 4];
    float m0=-1e30f,m1=-1e30f,m2=-1e30f,m3=-1e30f;
    float s0=0.f,s1=0.f,s2=0.f,s3=0.f;
    for (int j = start + lane; j < end; j += 32) {
        int src = g_esrc[j];
        float4 es = *(const float4*)&g_es1[src * 4];
        float e0 = lrelu(es.x + ed.x), e1 = lrelu(es.y + ed.y);
        float e2 = lrelu(es.z + ed.z), e3 = lrelu(es.w + ed.w);
        float n0 = fmaxf(m0,e0); s0 = s0*__expf(m0-n0)+__expf(e0-n0); m0=n0;
        float n1 = fmaxf(m1,e1); s1 = s1*__expf(m1-n1)+__expf(e1-n1); m1=n1;
        float n2 = fmaxf(m2,e2); s2 = s2*__expf(m2-n2)+__expf(e2-n2); m2=n2;
        float n3 = fmaxf(m3,e3); s3 = s3*__expf(m3-n3)+__expf(e3-n3); m3=n3;
    }
    #pragma unroll
    for (int off = 16; off; off >>= 1) {
        float mo, so, n;
        mo = __shfl_xor_sync(0xffffffffu, m0, off); so = __shfl_xor_sync(0xffffffffu, s0, off);
        n = fmaxf(m0, mo); s0 = s0*__expf(m0-n) + so*__expf(mo-n); m0 = n;
        mo = __shfl_xor_sync(0xffffffffu, m1, off); so = __shfl_xor_sync(0xffffffffu, s1, off);
        n = fmaxf(m1, mo); s1 = s1*__expf(m1-n) + so*__expf(mo-n); m1 = n;
        mo = __shfl_xor_sync(0xffffffffu, m2, off); so = __shfl_xor_sync(0xffffffffu, s2, off);
        n = fmaxf(m2, mo); s2 = s2*__expf(m2-n) + so*__expf(mo-n); m2 = n;
        mo = __shfl_xor_sync(0xffffffffu, m3, off); so = __shfl_xor_sync(0xffffffffu, s3, off);
        n = fmaxf(m3, mo); s3 = s3*__expf(m3-n) + so*__expf(mo-n); m3 = n;
    }
    if (lane == 0) {
        *(float4*)&g_m1[dst * 4] = make_float4(m0, m1, m2, m3);
        *(float4*)&g_i1[dst * 4] = make_float4(1.f/s0, 1.f/s1, 1.f/s2, 1.f/s3);
    }
}

__global__ __launch_bounds__(256) void stats2_kernel() {
    int dst  = (blockIdx.x * blockDim.x + threadIdx.x) >> 5;
    int lane = threadIdx.x & 31;
    if (dst >= NN) return;
    int start = g_off[dst], end = g_off[dst + 1];
    float edv = g_ed2[dst];
    float m = -1e30f, s = 0.f;
    for (int j = start + lane; j < end; j += 32) {
        int src = g_esrc[j];
        float e = lrelu(g_es2[src] + edv);
        float n = fmaxf(m, e); s = s*__expf(m-n) + __expf(e-n); m = n;
    }
    #pragma unroll
    for (int off = 16; off; off >>= 1) {
        float mo = __shfl_xor_sync(0xffffffffu, m, off);
        float so = __shfl_xor_sync(0xffffffffu, s, off);
        float n = fmaxf(m, mo); s = s*__expf(m-n) + so*__expf(mo-n); m = n;
    }
    if (lane == 0) { g_m2[dst] = m; g_i2[dst] = 1.f / s; }
}

// ---------------- aggregation: warp per dst, float4 gathers ------------------
__global__ __launch_bounds__(256) void agg1_kernel(const float* __restrict__ b1) {
    int dst  = (blockIdx.x * blockDim.x + threadIdx.x) >> 5;
    int lane = threadIdx.x & 31;
    if (dst >= NN) return;
    int start = g_off[dst], end = g_off[dst + 1];
    float4 ed = *(const float4*)&g_ed1[dst * 4];
    float4 m4 = *(const float4*)&g_m1[dst * 4];
    float4 i4 = *(const float4*)&g_i1[dst * 4];
    int hsel = lane >> 4;   // 0 or 1

    float4 acc0 = make_float4(0.f,0.f,0.f,0.f);
    float4 acc1 = make_float4(0.f,0.f,0.f,0.f);

    #pragma unroll 2
    for (int j = start; j < end; j++) {
        int src = g_esrc[j];
        float4 es = *(const float4*)&g_es1[src * 4];
        float w0 = __expf(lrelu(es.x + ed.x) - m4.x) * i4.x;
        float w1 = __expf(lrelu(es.y + ed.y) - m4.y) * i4.y;
        float w2 = __expf(lrelu(es.z + ed.z) - m4.z) * i4.z;
        float w3 = __expf(lrelu(es.w + ed.w) - m4.w) * i4.w;
        float wa = hsel ? w1 : w0;
        float wb = hsel ? w3 : w2;
        const float4* row = (const float4*)(g_h1 + (size_t)src * H1DIM);
        float4 v0 = row[lane];
        float4 v1 = row[lane + 32];
        acc0.x = fmaf(wa, v0.x, acc0.x); acc0.y = fmaf(wa, v0.y, acc0.y);
        acc0.z = fmaf(wa, v0.z, acc0.z); acc0.w = fmaf(wa, v0.w, acc0.w);
        acc1.x = fmaf(wb, v1.x, acc1.x); acc1.y = fmaf(wb, v1.y, acc1.y);
        acc1.z = fmaf(wb, v1.z, acc1.z); acc1.w = fmaf(wb, v1.w, acc1.w);
    }

    int c0 = lane * 4, c1 = 128 + lane * 4;
    float4 bb0 = *(const float4*)&b1[c0];
    float4 bb1 = *(const float4*)&b1[c1];
    float4 o0 = make_float4(elu1(acc0.x + bb0.x), elu1(acc0.y + bb0.y),
                            elu1(acc0.z + bb0.z), elu1(acc0.w + bb0.w));
    float4 o1 = make_float4(elu1(acc1.x + bb1.x), elu1(acc1.y + bb1.y),
                            elu1(acc1.z + bb1.z), elu1(acc1.w + bb1.w));
    *(float4*)(g_out1 + (size_t)dst * H1DIM + c0) = o0;
    *(float4*)(g_out1 + (size_t)dst * H1DIM + c1) = o1;
}

__global__ __launch_bounds__(256) void agg2_kernel(const float* __restrict__ b2) {
    int dst  = (blockIdx.x * blockDim.x + threadIdx.x) >> 5;
    int lane = threadIdx.x & 31;
    if (dst >= NN) return;
    int start = g_off[dst], end = g_off[dst + 1];
    float edv = g_ed2[dst];
    float m   = g_m2[dst];
    float inv = g_i2[dst];
    float4 acc = make_float4(0.f,0.f,0.f,0.f);

    #pragma unroll 2
    for (int j = start; j < end; j++) {
        int src = g_esrc[j];
        float e = lrelu(g_es2[src] + edv);
        float wt = __expf(e - m) * inv;
        const float4* row = (const float4*)(g_h2 + (size_t)src * H2DIM);
        float4 v = row[lane];
        acc.x = fmaf(wt, v.x, acc.x); acc.y = fmaf(wt, v.y, acc.y);
        acc.z = fmaf(wt, v.z, acc.z); acc.w = fmaf(wt, v.w, acc.w);
    }

    int c0 = lane * 4;
    float4 bb = *(const float4*)&b2[c0];
    float4 o = make_float4(elu1(acc.x + bb.x), elu1(acc.y + bb.y),
                           elu1(acc.z + bb.z), elu1(acc.w + bb.w));
    *(float4*)(g_out2 + (size_t)dst * H2DIM + c0) = o;
}

// ---------------- pooling + FC + log_softmax ---------------------------------
__device__ __forceinline__ int lb_i(const int* a, int n, int v) {
    int lo = 0, hi = n;
    while (lo < hi) { int mid = (lo + hi) >> 1; if (a[mid] < v) lo = mid + 1; else hi = mid; }
    return lo;
}

__global__ void pool_fc_kernel(const int* __restrict__ batch,
                               const float* __restrict__ fc_w,
                               const float* __restrict__ fc_b,
                               float* __restrict__ out)
{
    int g = blockIdx.x;
    int tid = threadIdx.x;
    __shared__ float sp[128];
    __shared__ float slog[10];
    int lo = lb_i(batch, NN, g);
    int hi = lb_i(batch, NN, g + 1);
    float s = 0.f;
    for (int i = lo; i < hi; i++) s += g_out2[(size_t)i * H2DIM + tid];
    float cnt = (float)(hi - lo);
    sp[tid] = s / fmaxf(cnt, 1.f);
    __syncthreads();
    if (tid < 10) {
        float l = fc_b[tid];
        #pragma unroll 16
        for (int c = 0; c < 128; c++) l = fmaf(sp[c], fc_w[c * 10 + tid], l);
        slog[tid] = l;
    }
    __syncthreads();
    if (tid == 0) {
        float mx = -1e30f;
        #pragma unroll
        for (int k = 0; k < 10; k++) mx = fmaxf(mx, slog[k]);
        float sum = 0.f;
        #pragma unroll
        for (int k = 0; k < 10; k++) sum += expf(slog[k] - mx);
        float lse = mx + logf(sum);
        #pragma unroll
        for (int k = 0; k < 10; k++) out[g * 10 + k] = slog[k] - lse;
    }
}

// ---------------- launch -----------------------------------------------------
extern "C" void kernel_launch(void* const* d_in, const int* in_sizes, int n_in,
                              void* d_out, int out_size)
{
    const float* x     = (const float*)d_in[0];
    const int*   ei    = (const int*)d_in[1];
    const int*   batch = (const int*)d_in[2];
    const float* W1    = (const float*)d_in[3];
    const float* a_s1  = (const float*)d_in[4];
    const float* a_d1  = (const float*)d_in[5];
    const float* b1    = (const float*)d_in[6];
    const float* W2    = (const float*)d_in[7];
    const float* a_s2  = (const float*)d_in[8];
    const float* a_d2  = (const float*)d_in[9];
    const float* b2    = (const float*)d_in[10];
    const float* fc_w  = (const float*)d_in[11];
    const float* fc_b  = (const float*)d_in[12];
    float* out = (float*)d_out;

    zero_counts_kernel<<<(NN + 255) / 256, 256>>>();
    count_kernel<<<(ET + 255) / 256, 256>>>(ei);
    scan1_kernel<<<NBLK, 1024>>>();
    scan2_kernel<<<1, 64>>>();
    scan3_kernel<<<(NN + 255) / 256, 256>>>();
    fill_kernel<<<(ET + 255) / 256, 256>>>(ei);

    {
        dim3 grid(H1DIM / BN, (NN + BM - 1) / BM);
        gemm1_kernel<<<grid, 256>>>(x, W1);
    }
    coef1_kernel<<<(NN * 4 + 255) / 256, 256>>>(a_s1, a_d1);
    stats1_kernel<<<(NN * 32 + 255) / 256, 256>>>();
    agg1_kernel<<<(NN * 32 + 255) / 256, 256>>>(b1);

    {
        dim3 grid(H2DIM / BN, (NN + BM - 1) / BM);
        gemm2_kernel<<<grid, 256>>>(W2);
    }
    coef2_kernel<<<(NN + 255) / 256, 256>>>(a_s2, a_d2);
    stats2_kernel<<<(NN * 32 + 255) / 256, 256>>>();
    agg2_kernel<<<(NN * 32 + 255) / 256, 256>>>(b2);

    pool_fc_kernel<<<NGRAPH, 128>>>(batch, fc_w, fc_b, out);
}

// round 8
// speedup vs baseline: 2.2832x; 1.0317x over previous
#include <cuda_runtime.h>
#include <cuda_fp16.h>
#include <math.h>
#include <stdint.h>

#define NN 50000
#define EE 800000
#define ET (EE + NN)
#define FIN 128
#define H1DIM 256
#define H2DIM 128
#define NGRAPH 64
#define NEG_SLOPE 0.2f
#define NBLK 49   // ceil(NN/1024)

// ---------------- scratch ----------------------------------------------------
__device__ __align__(16) float  g_h1[(size_t)NN * H1DIM];
__device__ __align__(16) __half g_h1h[(size_t)NN * H1DIM];
__device__ __align__(16) float  g_out1[(size_t)NN * H1DIM];
__device__ __align__(16) float  g_h2[(size_t)NN * H2DIM];
__device__ __align__(16) __half g_h2h[(size_t)NN * H2DIM];
__device__ __align__(16) float  g_out2[(size_t)NN * H2DIM];
__device__ __align__(16) float  g_es1[NN * 4];
__device__ __align__(16) float  g_ed1[NN * 4];
__device__ float g_es2[NN];
__device__ float g_ed2[NN];
__device__ int   g_cnt[NN];
__device__ int   g_off[NN + 1];
__device__ int   g_cur[NN];
__device__ int   g_esrc[ET];
__device__ int   g_bsum[NBLK];
__device__ int   g_boff[NBLK];

// ---------------- CSR build --------------------------------------------------
__global__ void zero_counts_kernel() {
    int i = blockIdx.x * blockDim.x + threadIdx.x;
    if (i < NN) g_cnt[i] = 0;
}

__global__ void count_kernel(const int* __restrict__ ei) {
    int e = blockIdx.x * blockDim.x + threadIdx.x;
    if (e >= ET) return;
    int dst = (e < EE) ? ei[EE + e] : (e - EE);
    atomicAdd(&g_cnt[dst], 1);
}

__global__ void scan1_kernel() {
    __shared__ int sdata[1024];
    int b = blockIdx.x, tid = threadIdx.x;
    int i = b * 1024 + tid;
    int v = (i < NN) ? g_cnt[i] : 0;
    sdata[tid] = v;
    __syncthreads();
    #pragma unroll
    for (int d = 1; d < 1024; d <<= 1) {
        int t = (tid >= d) ? sdata[tid - d] : 0;
        __syncthreads();
        sdata[tid] += t;
        __syncthreads();
    }
    if (i < NN) g_off[i] = sdata[tid] - v;
    if (tid == 1023) g_bsum[b] = sdata[1023];
}

__global__ void scan2_kernel() {
    int t = threadIdx.x;            // 64 threads
    int lane = t & 31, w = t >> 5;
    int v = (t < NBLK) ? g_bsum[t] : 0;
    int x = v;
    #pragma unroll
    for (int d = 1; d < 32; d <<= 1) {
        int y = __shfl_up_sync(0xffffffffu, x, d);
        if (lane >= d) x += y;
    }
    __shared__ int wt[2];
    if (lane == 31) wt[w] = x;
    __syncthreads();
    if (w == 1) x += wt[0];
    if (t < NBLK) g_boff[t] = x - v;
}

__global__ void scan3_kernel() {
    int i = blockIdx.x * blockDim.x + threadIdx.x;
    if (i >= NN) return;
    int v = g_off[i] + g_boff[i >> 10];
    g_off[i] = v;
    g_cur[i] = v;
    if (i == 0) g_off[NN] = ET;
}

__global__ void fill_kernel(const int* __restrict__ ei) {
    int e = blockIdx.x * blockDim.x + threadIdx.x;
    if (e >= ET) return;
    int src, dst;
    if (e < EE) { src = ei[e]; dst = ei[EE + e]; }
    else        { src = e - EE; dst = e - EE; }
    int pos = atomicAdd(&g_cur[dst], 1);
    g_esrc[pos] = src;
}

// ---------------- TF32 tensor-core GEMM, pre-split hi/lo in SMEM -------------
#define BM 128
#define BN 128
#define BK 8
#define PADK 8

__device__ __forceinline__ float4 ldg4(const float* p) { return *(const float4*)p; }

__device__ __forceinline__ uint32_t f2tf(float x) {
    uint32_t u;
    asm("cvt.rna.tf32.f32 %0, %1;" : "=r"(u) : "f"(x));
    return u;
}

__device__ __forceinline__ void mma8(float* c, const uint32_t* a, const uint32_t* b) {
    asm volatile(
        "mma.sync.aligned.m16n8k8.row.col.f32.tf32.tf32.f32 "
        "{%0,%1,%2,%3},{%4,%5,%6,%7},{%8,%9},{%0,%1,%2,%3};"
        : "+f"(c[0]), "+f"(c[1]), "+f"(c[2]), "+f"(c[3])
        : "r"(a[0]), "r"(a[1]), "r"(a[2]), "r"(a[3]), "r"(b[0]), "r"(b[1]));
}

__device__ __forceinline__ void gemm_body(
    const float* __restrict__ A, const float* __restrict__ B,
    float* __restrict__ C, __half* __restrict__ Ch, int M, int N, int K)
{
    __shared__ uint32_t Ahi[2][BK][BM + PADK];
    __shared__ uint32_t Alo[2][BK][BM + PADK];
    __shared__ uint32_t Bhi[2][BK][BN + PADK];
    __shared__ uint32_t Blo[2][BK][BN + PADK];

    const int tid  = threadIdx.x;
    const int lane = tid & 31;
    const int wid  = tid >> 5;
    const int warp_m = wid >> 2;
    const int warp_n = wid & 3;
    const int bm = blockIdx.y * BM, bn = blockIdx.x * BN;
    const int tg = lane & 3;
    const int tr = lane >> 2;

    const int ar = tid & 127, ac = (tid >> 7) * 4;
    const int br = tid >> 5, bc = (tid & 31) * 4;

    float c[4][4][4];
    #pragma unroll
    for (int mt = 0; mt < 4; mt++)
        #pragma unroll
        for (int nt = 0; nt < 4; nt++)
            #pragma unroll
            for (int r = 0; r < 4; r++) c[mt][nt][r] = 0.f;

    float4 pa, pb;
    auto LDG = [&](int k0) {
        pa = (bm + ar < M) ? ldg4(A + (size_t)(bm + ar) * K + k0 + ac) : make_float4(0.f,0.f,0.f,0.f);
        pb = ldg4(B + (size_t)(k0 + br) * N + bn + bc);
    };
    auto STS = [&](int buf) {
        float av[4] = {pa.x, pa.y, pa.z, pa.w};
        #pragma unroll
        for (int i = 0; i < 4; i++) {
            uint32_t hi = f2tf(av[i]);
            uint32_t lo = f2tf(av[i] - __uint_as_float(hi));
            Ahi[buf][ac + i][ar] = hi;
            Alo[buf][ac + i][ar] = lo;
        }
        float bv[4] = {pb.x, pb.y, pb.z, pb.w};
        uint32_t h0 = f2tf(bv[0]), h1 = f2tf(bv[1]), h2 = f2tf(bv[2]), h3 = f2tf(bv[3]);
        *(uint4*)&Bhi[buf][br][bc] = make_uint4(h0, h1, h2, h3);
        *(uint4*)&Blo[buf][br][bc] = make_uint4(
            f2tf(bv[0] - __uint_as_float(h0)),
            f2tf(bv[1] - __uint_as_float(h1)),
            f2tf(bv[2] - __uint_as_float(h2)),
            f2tf(bv[3] - __uint_as_float(h3)));
    };

    LDG(0);
    STS(0);
    __syncthreads();

    const int T = K / BK;
    for (int t = 0; t < T; t++) {
        int cur = t & 1;
        if (t + 1 < T) LDG((t + 1) * BK);

        uint32_t ahi[4][4], alo[4][4], bhi[4][2], blo[4][2];
        #pragma unroll
        for (int mt = 0; mt < 4; mt++) {
            int mb = warp_m * 64 + mt * 16;
            ahi[mt][0] = Ahi[cur][tg    ][mb + tr];
            ahi[mt][1] = Ahi[cur][tg    ][mb + tr + 8];
            ahi[mt][2] = Ahi[cur][tg + 4][mb + tr];
            ahi[mt][3] = Ahi[cur][tg + 4][mb + tr + 8];
            alo[mt][0] = Alo[cur][tg    ][mb + tr];
            alo[mt][1] = Alo[cur][tg    ][mb + tr + 8];
            alo[mt][2] = Alo[cur][tg + 4][mb + tr];
            alo[mt][3] = Alo[cur][tg + 4][mb + tr + 8];
        }
        #pragma unroll
        for (int nt = 0; nt < 4; nt++) {
            int nb = warp_n * 32 + nt * 8;
            bhi[nt][0] = Bhi[cur][tg    ][nb + tr];
            bhi[nt][1] = Bhi[cur][tg + 4][nb + tr];
            blo[nt][0] = Blo[cur][tg    ][nb + tr];
            blo[nt][1] = Blo[cur][tg + 4][nb + tr];
        }
        #pragma unroll
        for (int mt = 0; mt < 4; mt++)
            #pragma unroll
            for (int nt = 0; nt < 4; nt++) {
                mma8(c[mt][nt], ahi[mt], bhi[nt]);
                mma8(c[mt][nt], alo[mt], bhi[nt]);
                mma8(c[mt][nt], ahi[mt], blo[nt]);
            }

        if (t + 1 < T) { STS(cur ^ 1); __syncthreads(); }
    }

    #pragma unroll
    for (int mt = 0; mt < 4; mt++) {
        int row0 = bm + warp_m * 64 + mt * 16 + tr;
        int row1 = row0 + 8;
        #pragma unroll
        for (int nt = 0; nt < 4; nt++) {
            int col = bn + warp_n * 32 + nt * 8 + tg * 2;
            if (row0 < M) {
                *(float2*)(C + (size_t)row0 * N + col) = make_float2(c[mt][nt][0], c[mt][nt][1]);
                *(__half2*)(Ch + (size_t)row0 * N + col) =
                    __float22half2_rn(make_float2(c[mt][nt][0], c[mt][nt][1]));
            }
            if (row1 < M) {
                *(float2*)(C + (size_t)row1 * N + col) = make_float2(c[mt][nt][2], c[mt][nt][3]);
                *(__half2*)(Ch + (size_t)row1 * N + col) =
                    __float22half2_rn(make_float2(c[mt][nt][2], c[mt][nt][3]));
            }
        }
    }
}

__global__ __launch_bounds__(256) void gemm1_kernel(
    const float* __restrict__ x, const float* __restrict__ W1)
{
    gemm_body(x, W1, g_h1, g_h1h, NN, H1DIM, FIN);
}

__global__ __launch_bounds__(256) void gemm2_kernel(
    const float* __restrict__ W2)
{
    gemm_body(g_out1, W2, g_h2, g_h2h, NN, H2DIM, H1DIM);
}

// ---------------- attention coefficients ------------------------------------
__global__ void coef1_kernel(const float* __restrict__ a_s, const float* __restrict__ a_d) {
    int idx = blockIdx.x * blockDim.x + threadIdx.x;
    if (idx >= NN * 4) return;
    int node = idx >> 2, head = idx & 3;
    const float* row = g_h1 + (size_t)node * H1DIM + head * 64;
    const float* as = a_s + head * 64;
    const float* ad = a_d + head * 64;
    float s = 0.f, d = 0.f;
    #pragma unroll 16
    for (int c = 0; c < 64; c++) {
        float h = row[c];
        s = fmaf(h, as[c], s);
        d = fmaf(h, ad[c], d);
    }
    g_es1[idx] = s;
    g_ed1[idx] = d;
}

__global__ void coef2_kernel(const float* __restrict__ a_s, const float* __restrict__ a_d) {
    int node = blockIdx.x * blockDim.x + threadIdx.x;
    if (node >= NN) return;
    const float* row = g_h2 + (size_t)node * H2DIM;
    float s = 0.f, d = 0.f;
    #pragma unroll 16
    for (int c = 0; c < 128; c++) {
        float h = row[c];
        s = fmaf(h, a_s[c], s);
        d = fmaf(h, a_d[c], d);
    }
    g_es2[node] = s;
    g_ed2[node] = d;
}

__device__ __forceinline__ float elu1(float x)  { return x > 0.f ? x : expm1f(x); }
__device__ __forceinline__ float lrelu(float x) { return x > 0.f ? x : NEG_SLOPE * x; }

// ---------------- fused stats + aggregation (warp per dst) -------------------
__global__ __launch_bounds__(256) void agg1_kernel(const float* __restrict__ b1) {
    int dst  = (blockIdx.x * blockDim.x + threadIdx.x) >> 5;
    int lane = threadIdx.x & 31;
    if (dst >= NN) return;
    int start = g_off[dst], end = g_off[dst + 1];
    float4 ed = *(const float4*)&g_ed1[dst * 4];

    // ---- pass A: lane-parallel online softmax stats ----
    float m0=-1e30f,m1=-1e30f,m2=-1e30f,m3=-1e30f;
    float s0=0.f,s1=0.f,s2=0.f,s3=0.f;
    for (int j = start + lane; j < end; j += 32) {
        int src = g_esrc[j];
        float4 es = *(const float4*)&g_es1[src * 4];
        float e0 = lrelu(es.x + ed.x), e1 = lrelu(es.y + ed.y);
        float e2 = lrelu(es.z + ed.z), e3 = lrelu(es.w + ed.w);
        float n0 = fmaxf(m0,e0); s0 = s0*__expf(m0-n0)+__expf(e0-n0); m0=n0;
        float n1 = fmaxf(m1,e1); s1 = s1*__expf(m1-n1)+__expf(e1-n1); m1=n1;
        float n2 = fmaxf(m2,e2); s2 = s2*__expf(m2-n2)+__expf(e2-n2); m2=n2;
        float n3 = fmaxf(m3,e3); s3 = s3*__expf(m3-n3)+__expf(e3-n3); m3=n3;
    }
    #pragma unroll
    for (int off = 16; off; off >>= 1) {
        float mo, so, n;
        mo = __shfl_xor_sync(0xffffffffu, m0, off); so = __shfl_xor_sync(0xffffffffu, s0, off);
        n = fmaxf(m0, mo); s0 = s0*__expf(m0-n) + so*__expf(mo-n); m0 = n;
        mo = __shfl_xor_sync(0xffffffffu, m1, off); so = __shfl_xor_sync(0xffffffffu, s1, off);
        n = fmaxf(m1, mo); s1 = s1*__expf(m1-n) + so*__expf(mo-n); m1 = n;
        mo = __shfl_xor_sync(0xffffffffu, m2, off); so = __shfl_xor_sync(0xffffffffu, s2, off);
        n = fmaxf(m2, mo); s2 = s2*__expf(m2-n) + so*__expf(mo-n); m2 = n;
        mo = __shfl_xor_sync(0xffffffffu, m3, off); so = __shfl_xor_sync(0xffffffffu, s3, off);
        n = fmaxf(m3, mo); s3 = s3*__expf(m3-n) + so*__expf(mo-n); m3 = n;
    }
    float i0 = 1.f/s0, i1 = 1.f/s1, i2 = 1.f/s2, i3 = 1.f/s3;

    // ---- pass B: serial edges, feature-parallel half gathers ----
    int hsel = lane >> 4;
    float ma = hsel ? m1 : m0, mb = hsel ? m3 : m2;
    float ia = hsel ? i1 : i0, ib = hsel ? i3 : i2;
    float eda = hsel ? ed.y : ed.x, edb = hsel ? ed.w : ed.z;

    float4 acc0 = make_float4(0.f,0.f,0.f,0.f);
    float4 acc1 = make_float4(0.f,0.f,0.f,0.f);

    #pragma unroll 2
    for (int j = start; j < end; j++) {
        int src = g_esrc[j];
        float2 esa = hsel ? *(const float2*)&g_es1[src*4+1-1+1]  // placeholder avoided below
                          : make_float2(0.f,0.f);
        // gather both needed es lanes directly:
        float es_a = g_es1[src * 4 + hsel];        // head 0 or 1
        float es_b = g_es1[src * 4 + 2 + hsel];    // head 2 or 3
        float wa = __expf(lrelu(es_a + eda) - ma) * ia;
        float wb = __expf(lrelu(es_b + edb) - mb) * ib;
        const __half2* row = (const __half2*)(g_h1h + (size_t)src * H1DIM);
        __half2 p0 = row[lane * 2],      p1 = row[lane * 2 + 1];
        __half2 p2 = row[64 + lane * 2], p3 = row[64 + lane * 2 + 1];
        float2 f0 = __half22float2(p0), f1 = __half22float2(p1);
        float2 f2 = __half22float2(p2), f3 = __half22float2(p3);
        acc0.x = fmaf(wa, f0.x, acc0.x); acc0.y = fmaf(wa, f0.y, acc0.y);
        acc0.z = fmaf(wa, f1.x, acc0.z); acc0.w = fmaf(wa, f1.y, acc0.w);
        acc1.x = fmaf(wb, f2.x, acc1.x); acc1.y = fmaf(wb, f2.y, acc1.y);
        acc1.z = fmaf(wb, f3.x, acc1.z); acc1.w = fmaf(wb, f3.y, acc1.w);
    }

    int c0 = lane * 4, c1 = 128 + lane * 4;
    float4 bb0 = *(const float4*)&b1[c0];
    float4 bb1 = *(const float4*)&b1[c1];
    float4 o0 = make_float4(elu1(acc0.x + bb0.x), elu1(acc0.y + bb0.y),
                            elu1(acc0.z + bb0.z), elu1(acc0.w + bb0.w));
    float4 o1 = make_float4(elu1(acc1.x + bb1.x), elu1(acc1.y + bb1.y),
                            elu1(acc1.z + bb1.z), elu1(acc1.w + bb1.w));
    *(float4*)(g_out1 + (size_t)dst * H1DIM + c0) = o0;
    *(float4*)(g_out1 + (size_t)dst * H1DIM + c1) = o1;
}

__global__ __launch_bounds__(256) void agg2_kernel(const float* __restrict__ b2) {
    int dst  = (blockIdx.x * blockDim.x + threadIdx.x) >> 5;
    int lane = threadIdx.x & 31;
    if (dst >= NN) return;
    int start = g_off[dst], end = g_off[dst + 1];
    float edv = g_ed2[dst];

    // pass A: stats
    float m = -1e30f, s = 0.f;
    for (int j = start + lane; j < end; j += 32) {
        int src = g_esrc[j];
        float e = lrelu(g_es2[src] + edv);
        float n = fmaxf(m, e); s = s*__expf(m-n) + __expf(e-n); m = n;
    }
    #pragma unroll
    for (int off = 16; off; off >>= 1) {
        float mo = __shfl_xor_sync(0xffffffffu, m, off);
        float so = __shfl_xor_sync(0xffffffffu, s, off);
        float n = fmaxf(m, mo); s = s*__expf(m-n) + so*__expf(mo-n); m = n;
    }
    float inv = 1.f / s;

    // pass B: accumulate
    float4 acc = make_float4(0.f,0.f,0.f,0.f);
    #pragma unroll 2
    for (int j = start; j < end; j++) {
        int src = g_esrc[j];
        float e = lrelu(g_es2[src] + edv);
        float wt = __expf(e - m) * inv;
        const __half2* row = (const __half2*)(g_h2h + (size_t)src * H2DIM);
        __half2 p0 = row[lane * 2], p1 = row[lane * 2 + 1];
        float2 f0 = __half22float2(p0), f1 = __half22float2(p1);
        acc.x = fmaf(wt, f0.x, acc.x); acc.y = fmaf(wt, f0.y, acc.y);
        acc.z = fmaf(wt, f1.x, acc.z); acc.w = fmaf(wt, f1.y, acc.w);
    }

    int c0 = lane * 4;
    float4 bb = *(const float4*)&b2[c0];
    float4 o = make_float4(elu1(acc.x + bb.x), elu1(acc.y + bb.y),
                           elu1(acc.z + bb.z), elu1(acc.w + bb.w));
    *(float4*)(g_out2 + (size_t)dst * H2DIM + c0) = o;
}

// ---------------- pooling + FC + log_softmax ---------------------------------
__device__ __forceinline__ int lb_i(const int* a, int n, int v) {
    int lo = 0, hi = n;
    while (lo < hi) { int mid = (lo + hi) >> 1; if (a[mid] < v) lo = mid + 1; else hi = mid; }
    return lo;
}

__global__ void pool_fc_kernel(const int* __restrict__ batch,
                               const float* __restrict__ fc_w,
                               const float* __restrict__ fc_b,
                               float* __restrict__ out)
{
    int g = blockIdx.x;
    int tid = threadIdx.x;
    __shared__ float sp[128];
    __shared__ float slog[10];
    int lo = lb_i(batch, NN, g);
    int hi = lb_i(batch, NN, g + 1);
    float s = 0.f;
    for (int i = lo; i < hi; i++) s += g_out2[(size_t)i * H2DIM + tid];
    float cnt = (float)(hi - lo);
    sp[tid] = s / fmaxf(cnt, 1.f);
    __syncthreads();
    if (tid < 10) {
        float l = fc_b[tid];
        #pragma unroll 16
        for (int c = 0; c < 128; c++) l = fmaf(sp[c], fc_w[c * 10 + tid], l);
        slog[tid] = l;
    }
    __syncthreads();
    if (tid == 0) {
        float mx = -1e30f;
        #pragma unroll
        for (int k = 0; k < 10; k++) mx = fmaxf(mx, slog[k]);
        float sum = 0.f;
        #pragma unroll
        for (int k = 0; k < 10; k++) sum += expf(slog[k] - mx);
        float lse = mx + logf(sum);
        #pragma unroll
        for (int k = 0; k < 10; k++) out[g * 10 + k] = slog[k] - lse;
    }
}

// ---------------- launch -----------------------------------------------------
extern "C" void kernel_launch(void* const* d_in, const int* in_sizes, int n_in,
                              void* d_out, int out_size)
{
    const float* x     = (const float*)d_in[0];
    const int*   ei    = (const int*)d_in[1];
    const int*   batch = (const int*)d_in[2];
    const float* W1    = (const float*)d_in[3];
    const float* a_s1  = (const float*)d_in[4];
    const float* a_d1  = (const float*)d_in[5];
    const float* b1    = (const float*)d_in[6];
    const float* W2    = (const float*)d_in[7];
    const float* a_s2  = (const float*)d_in[8];
    const float* a_d2  = (const float*)d_in[9];
    const float* b2    = (const float*)d_in[10];
    const float* fc_w  = (const float*)d_in[11];
    const float* fc_b  = (const float*)d_in[12];
    float* out = (float*)d_out;

    zero_counts_kernel<<<(NN + 255) / 256, 256>>>();
    count_kernel<<<(ET + 255) / 256, 256>>>(ei);
    scan1_kernel<<<NBLK, 1024>>>();
    scan2_kernel<<<1, 64>>>();
    scan3_kernel<<<(NN + 255) / 256, 256>>>();
    fill_kernel<<<(ET + 255) / 256, 256>>>(ei);

    {
        dim3 grid(H1DIM / BN, (NN + BM - 1) / BM);
        gemm1_kernel<<<grid, 256>>>(x, W1);
    }
    coef1_kernel<<<(NN * 4 + 255) / 256, 256>>>(a_s1, a_d1);
    agg1_kernel<<<(NN * 32 + 255) / 256, 256>>>(b1);

    {
        dim3 grid(H2DIM / BN, (NN + BM - 1) / BM);
        gemm2_kernel<<<grid, 256>>>(W2);
    }
    coef2_kernel<<<(NN + 255) / 256, 256>>>(a_s2, a_d2);
    agg2_kernel<<<(NN * 32 + 255) / 256, 256>>>(b2);

    pool_fc_kernel<<<NGRAPH, 128>>>(batch, fc_w, fc_b, out);
}

// round 9
// speedup vs baseline: 2.5942x; 1.1362x over previous
#include <cuda_runtime.h>
#include <cuda_fp16.h>
#include <math.h>
#include <stdint.h>

#define NN 50000
#define EE 800000
#define ET (EE + NN)
#define FIN 128
#define H1DIM 256
#define H2DIM 128
#define NGRAPH 64
#define NEG_SLOPE 0.2f
#define NBLK 49   // ceil(NN/1024)

// ---------------- scratch ----------------------------------------------------
__device__ __align__(16) float  g_h1[(size_t)NN * H1DIM];
__device__ __align__(16) __half g_h1h[(size_t)NN * H1DIM];
__device__ __align__(16) float  g_out1[(size_t)NN * H1DIM];
__device__ __align__(16) float  g_h2[(size_t)NN * H2DIM];
__device__ __align__(16) __half g_h2h[(size_t)NN * H2DIM];
__device__ __align__(16) float  g_out2[(size_t)NN * H2DIM];
__device__ __align__(16) float  g_es1[NN * 4];
__device__ __align__(16) float  g_ed1[NN * 4];
__device__ float g_es2[NN];
__device__ float g_ed2[NN];
__device__ int   g_cnt[NN];
__device__ int   g_off[NN + 1];
__device__ int   g_cur[NN];
__device__ int   g_esrc[ET];
__device__ int   g_bsum[NBLK];
__device__ int   g_boff[NBLK];

// ---------------- CSR build --------------------------------------------------
__global__ void zero_counts_kernel() {
    int i = blockIdx.x * blockDim.x + threadIdx.x;
    if (i < NN) g_cnt[i] = 0;
}

__global__ void count_kernel(const int* __restrict__ ei) {
    int e = blockIdx.x * blockDim.x + threadIdx.x;
    if (e >= ET) return;
    int dst = (e < EE) ? ei[EE + e] : (e - EE);
    atomicAdd(&g_cnt[dst], 1);
}

__global__ void scan1_kernel() {
    __shared__ int sdata[1024];
    int b = blockIdx.x, tid = threadIdx.x;
    int i = b * 1024 + tid;
    int v = (i < NN) ? g_cnt[i] : 0;
    sdata[tid] = v;
    __syncthreads();
    #pragma unroll
    for (int d = 1; d < 1024; d <<= 1) {
        int t = (tid >= d) ? sdata[tid - d] : 0;
        __syncthreads();
        sdata[tid] += t;
        __syncthreads();
    }
    if (i < NN) g_off[i] = sdata[tid] - v;
    if (tid == 1023) g_bsum[b] = sdata[1023];
}

__global__ void scan2_kernel() {
    int t = threadIdx.x;            // 64 threads
    int lane = t & 31, w = t >> 5;
    int v = (t < NBLK) ? g_bsum[t] : 0;
    int x = v;
    #pragma unroll
    for (int d = 1; d < 32; d <<= 1) {
        int y = __shfl_up_sync(0xffffffffu, x, d);
        if (lane >= d) x += y;
    }
    __shared__ int wt[2];
    if (lane == 31) wt[w] = x;
    __syncthreads();
    if (w == 1) x += wt[0];
    if (t < NBLK) g_boff[t] = x - v;
}

__global__ void scan3_kernel() {
    int i = blockIdx.x * blockDim.x + threadIdx.x;
    if (i >= NN) return;
    int v = g_off[i] + g_boff[i >> 10];
    g_off[i] = v;
    g_cur[i] = v;
    if (i == 0) g_off[NN] = ET;
}

__global__ void fill_kernel(const int* __restrict__ ei) {
    int e = blockIdx.x * blockDim.x + threadIdx.x;
    if (e >= ET) return;
    int src, dst;
    if (e < EE) { src = ei[e]; dst = ei[EE + e]; }
    else        { src = e - EE; dst = e - EE; }
    int pos = atomicAdd(&g_cur[dst], 1);
    g_esrc[pos] = src;
}

// ---------------- single-pass TF32 tensor-core GEMM --------------------------
#define BM 128
#define BN 128
#define BK 16
#define PADK 8

__device__ __forceinline__ float4 ldg4(const float* p) { return *(const float4*)p; }

__device__ __forceinline__ uint32_t f2tf(float x) {
    uint32_t u;
    asm("cvt.rna.tf32.f32 %0, %1;" : "=r"(u) : "f"(x));
    return u;
}

__device__ __forceinline__ void mma8(float* c, const uint32_t* a, const uint32_t* b) {
    asm volatile(
        "mma.sync.aligned.m16n8k8.row.col.f32.tf32.tf32.f32 "
        "{%0,%1,%2,%3},{%4,%5,%6,%7},{%8,%9},{%0,%1,%2,%3};"
        : "+f"(c[0]), "+f"(c[1]), "+f"(c[2]), "+f"(c[3])
        : "r"(a[0]), "r"(a[1]), "r"(a[2]), "r"(a[3]), "r"(b[0]), "r"(b[1]));
}

__device__ __forceinline__ void gemm_body(
    const float* __restrict__ A, const float* __restrict__ B,
    float* __restrict__ C, __half* __restrict__ Ch, int M, int N, int K)
{
    __shared__ uint32_t Ahi[2][BK][BM + PADK];
    __shared__ uint32_t Bhi[2][BK][BN + PADK];

    const int tid  = threadIdx.x;
    const int lane = tid & 31;
    const int wid  = tid >> 5;
    const int warp_m = wid >> 2;
    const int warp_n = wid & 3;
    const int bm = blockIdx.y * BM, bn = blockIdx.x * BN;
    const int tg = lane & 3;
    const int tr = lane >> 2;

    // A loader: 128 rows x 16 cols, 8 floats per thread (2 float4)
    const int ar = tid & 127, ac = (tid >> 7) * 8;
    // B loader: 16 rows x 128 cols, 8 floats per thread (2 float4)
    const int br = tid >> 4, bc = (tid & 15) * 8;

    float c[4][4][4];
    #pragma unroll
    for (int mt = 0; mt < 4; mt++)
        #pragma unroll
        for (int nt = 0; nt < 4; nt++)
            #pragma unroll
            for (int r = 0; r < 4; r++) c[mt][nt][r] = 0.f;

    float4 pa0, pa1, pb0, pb1;
    auto LDG = [&](int k0) {
        if (bm + ar < M) {
            pa0 = ldg4(A + (size_t)(bm + ar) * K + k0 + ac);
            pa1 = ldg4(A + (size_t)(bm + ar) * K + k0 + ac + 4);
        } else {
            pa0 = make_float4(0.f,0.f,0.f,0.f);
            pa1 = pa0;
        }
        pb0 = ldg4(B + (size_t)(k0 + br) * N + bn + bc);
        pb1 = ldg4(B + (size_t)(k0 + br) * N + bn + bc + 4);
    };
    auto STS = [&](int buf) {
        float av[8] = {pa0.x, pa0.y, pa0.z, pa0.w, pa1.x, pa1.y, pa1.z, pa1.w};
        #pragma unroll
        for (int i = 0; i < 8; i++)
            Ahi[buf][ac + i][ar] = f2tf(av[i]);
        *(uint4*)&Bhi[buf][br][bc] =
            make_uint4(f2tf(pb0.x), f2tf(pb0.y), f2tf(pb0.z), f2tf(pb0.w));
        *(uint4*)&Bhi[buf][br][bc + 4] =
            make_uint4(f2tf(pb1.x), f2tf(pb1.y), f2tf(pb1.z), f2tf(pb1.w));
    };

    LDG(0);
    STS(0);
    __syncthreads();

    const int T = K / BK;
    for (int t = 0; t < T; t++) {
        int cur = t & 1;
        if (t + 1 < T) LDG((t + 1) * BK);

        #pragma unroll
        for (int ks = 0; ks < 2; ks++) {
            const int kk = ks * 8;
            uint32_t a[4][4], b[4][2];
            #pragma unroll
            for (int mt = 0; mt < 4; mt++) {
                int mb = warp_m * 64 + mt * 16;
                a[mt][0] = Ahi[cur][kk + tg    ][mb + tr];
                a[mt][1] = Ahi[cur][kk + tg    ][mb + tr + 8];
                a[mt][2] = Ahi[cur][kk + tg + 4][mb + tr];
                a[mt][3] = Ahi[cur][kk + tg + 4][mb + tr + 8];
            }
            #pragma unroll
            for (int nt = 0; nt < 4; nt++) {
                int nb = warp_n * 32 + nt * 8;
                b[nt][0] = Bhi[cur][kk + tg    ][nb + tr];
                b[nt][1] = Bhi[cur][kk + tg + 4][nb + tr];
            }
            #pragma unroll
            for (int mt = 0; mt < 4; mt++)
                #pragma unroll
                for (int nt = 0; nt < 4; nt++)
                    mma8(c[mt][nt], a[mt], b[nt]);
        }

        if (t + 1 < T) { STS(cur ^ 1); __syncthreads(); }
    }

    #pragma unroll
    for (int mt = 0; mt < 4; mt++) {
        int row0 = bm + warp_m * 64 + mt * 16 + tr;
        int row1 = row0 + 8;
        #pragma unroll
        for (int nt = 0; nt < 4; nt++) {
            int col = bn + warp_n * 32 + nt * 8 + tg * 2;
            if (row0 < M) {
                *(float2*)(C + (size_t)row0 * N + col) = make_float2(c[mt][nt][0], c[mt][nt][1]);
                *(__half2*)(Ch + (size_t)row0 * N + col) =
                    __float22half2_rn(make_float2(c[mt][nt][0], c[mt][nt][1]));
            }
            if (row1 < M) {
                *(float2*)(C + (size_t)row1 * N + col) = make_float2(c[mt][nt][2], c[mt][nt][3]);
                *(__half2*)(Ch + (size_t)row1 * N + col) =
                    __float22half2_rn(make_float2(c[mt][nt][2], c[mt][nt][3]));
            }
        }
    }
}

__global__ __launch_bounds__(256) void gemm1_kernel(
    const float* __restrict__ x, const float* __restrict__ W1)
{
    gemm_body(x, W1, g_h1, g_h1h, NN, H1DIM, FIN);
}

__global__ __launch_bounds__(256) void gemm2_kernel(
    const float* __restrict__ W2)
{
    gemm_body(g_out1, W2, g_h2, g_h2h, NN, H2DIM, H1DIM);
}

// ---------------- attention coefficients ------------------------------------
__global__ void coef1_kernel(const float* __restrict__ a_s, const float* __restrict__ a_d) {
    int idx = blockIdx.x * blockDim.x + threadIdx.x;
    if (idx >= NN * 4) return;
    int node = idx >> 2, head = idx & 3;
    const float4* row = (const float4*)(g_h1 + (size_t)node * H1DIM + head * 64);
    const float4* as = (const float4*)(a_s + head * 64);
    const float4* ad = (const float4*)(a_d + head * 64);
    float s = 0.f, d = 0.f;
    #pragma unroll
    for (int c = 0; c < 16; c++) {
        float4 h = row[c];
        float4 sa = as[c], da = ad[c];
        s = fmaf(h.x, sa.x, fmaf(h.y, sa.y, fmaf(h.z, sa.z, fmaf(h.w, sa.w, s))));
        d = fmaf(h.x, da.x, fmaf(h.y, da.y, fmaf(h.z, da.z, fmaf(h.w, da.w, d))));
    }
    g_es1[idx] = s;
    g_ed1[idx] = d;
}

__global__ void coef2_kernel(const float* __restrict__ a_s, const float* __restrict__ a_d) {
    int node = blockIdx.x * blockDim.x + threadIdx.x;
    if (node >= NN) return;
    const float4* row = (const float4*)(g_h2 + (size_t)node * H2DIM);
    const float4* as = (const float4*)a_s;
    const float4* ad = (const float4*)a_d;
    float s = 0.f, d = 0.f;
    #pragma unroll
    for (int c = 0; c < 32; c++) {
        float4 h = row[c];
        float4 sa = as[c], da = ad[c];
        s = fmaf(h.x, sa.x, fmaf(h.y, sa.y, fmaf(h.z, sa.z, fmaf(h.w, sa.w, s))));
        d = fmaf(h.x, da.x, fmaf(h.y, da.y, fmaf(h.z, da.z, fmaf(h.w, da.w, d))));
    }
    g_es2[node] = s;
    g_ed2[node] = d;
}

__device__ __forceinline__ float elu1(float x)  { return x > 0.f ? x : expm1f(x); }
__device__ __forceinline__ float lrelu(float x) { return x > 0.f ? x : NEG_SLOPE * x; }

// ---------------- fused stats + aggregation (warp per dst) -------------------
__global__ __launch_bounds__(256) void agg1_kernel(const float* __restrict__ b1) {
    int dst  = (blockIdx.x * blockDim.x + threadIdx.x) >> 5;
    int lane = threadIdx.x & 31;
    if (dst >= NN) return;
    int start = g_off[dst], end = g_off[dst + 1];
    float4 ed = *(const float4*)&g_ed1[dst * 4];

    // pass A: lane-parallel online softmax stats
    float m0=-1e30f,m1=-1e30f,m2=-1e30f,m3=-1e30f;
    float s0=0.f,s1=0.f,s2=0.f,s3=0.f;
    for (int j = start + lane; j < end; j += 32) {
        int src = g_esrc[j];
        float4 es = *(const float4*)&g_es1[src * 4];
        float e0 = lrelu(es.x + ed.x), e1 = lrelu(es.y + ed.y);
        float e2 = lrelu(es.z + ed.z), e3 = lrelu(es.w + ed.w);
        float n0 = fmaxf(m0,e0); s0 = s0*__expf(m0-n0)+__expf(e0-n0); m0=n0;
        float n1 = fmaxf(m1,e1); s1 = s1*__expf(m1-n1)+__expf(e1-n1); m1=n1;
        float n2 = fmaxf(m2,e2); s2 = s2*__expf(m2-n2)+__expf(e2-n2); m2=n2;
        float n3 = fmaxf(m3,e3); s3 = s3*__expf(m3-n3)+__expf(e3-n3); m3=n3;
    }
    #pragma unroll
    for (int off = 16; off; off >>= 1) {
        float mo, so, n;
        mo = __shfl_xor_sync(0xffffffffu, m0, off); so = __shfl_xor_sync(0xffffffffu, s0, off);
        n = fmaxf(m0, mo); s0 = s0*__expf(m0-n) + so*__expf(mo-n); m0 = n;
        mo = __shfl_xor_sync(0xffffffffu, m1, off); so = __shfl_xor_sync(0xffffffffu, s1, off);
        n = fmaxf(m1, mo); s1 = s1*__expf(m1-n) + so*__expf(mo-n); m1 = n;
        mo = __shfl_xor_sync(0xffffffffu, m2, off); so = __shfl_xor_sync(0xffffffffu, s2, off);
        n = fmaxf(m2, mo); s2 = s2*__expf(m2-n) + so*__expf(mo-n); m2 = n;
        mo = __shfl_xor_sync(0xffffffffu, m3, off); so = __shfl_xor_sync(0xffffffffu, s3, off);
        n = fmaxf(m3, mo); s3 = s3*__expf(m3-n) + so*__expf(mo-n); m3 = n;
    }
    float i0 = 1.f/s0, i1 = 1.f/s1, i2 = 1.f/s2, i3 = 1.f/s3;

    // pass B: serial edges, feature-parallel half gathers
    int hsel = lane >> 4;
    float ma = hsel ? m1 : m0, mb = hsel ? m3 : m2;
    float ia = hsel ? i1 : i0, ib = hsel ? i3 : i2;
    float eda = hsel ? ed.y : ed.x, edb = hsel ? ed.w : ed.z;

    float4 acc0 = make_float4(0.f,0.f,0.f,0.f);
    float4 acc1 = make_float4(0.f,0.f,0.f,0.f);

    #pragma unroll 4
    for (int j = start; j < end; j++) {
        int src = g_esrc[j];
        float4 es = *(const float4*)&g_es1[src * 4];
        float es_a = hsel ? es.y : es.x;
        float es_b = hsel ? es.w : es.z;
        float wa = __expf(lrelu(es_a + eda) - ma) * ia;
        float wb = __expf(lrelu(es_b + edb) - mb) * ib;
        const float2* row = (const float2*)(g_h1h + (size_t)src * H1DIM);
        float2 q0 = row[lane];        // halfs [4*lane .. 4*lane+3]
        float2 q1 = row[lane + 32];   // halfs [128+4*lane ..]
        float2 f0 = __half22float2(*(__half2*)&q0.x);
        float2 f1 = __half22float2(*(__half2*)&q0.y);
        float2 f2 = __half22float2(*(__half2*)&q1.x);
        float2 f3 = __half22float2(*(__half2*)&q1.y);
        acc0.x = fmaf(wa, f0.x, acc0.x); acc0.y = fmaf(wa, f0.y, acc0.y);
        acc0.z = fmaf(wa, f1.x, acc0.z); acc0.w = fmaf(wa, f1.y, acc0.w);
        acc1.x = fmaf(wb, f2.x, acc1.x); acc1.y = fmaf(wb, f2.y, acc1.y);
        acc1.z = fmaf(wb, f3.x, acc1.z); acc1.w = fmaf(wb, f3.y, acc1.w);
    }

    int c0 = lane * 4, c1 = 128 + lane * 4;
    float4 bb0 = *(const float4*)&b1[c0];
    float4 bb1 = *(const float4*)&b1[c1];
    float4 o0 = make_float4(elu1(acc0.x + bb0.x), elu1(acc0.y + bb0.y),
                            elu1(acc0.z + bb0.z), elu1(acc0.w + bb0.w));
    float4 o1 = make_float4(elu1(acc1.x + bb1.x), elu1(acc1.y + bb1.y),
                            elu1(acc1.z + bb1.z), elu1(acc1.w + bb1.w));
    *(float4*)(g_out1 + (size_t)dst * H1DIM + c0) = o0;
    *(float4*)(g_out1 + (size_t)dst * H1DIM + c1) = o1;
}

__global__ __launch_bounds__(256) void agg2_kernel(const float* __restrict__ b2) {
    int dst  = (blockIdx.x * blockDim.x + threadIdx.x) >> 5;
    int lane = threadIdx.x & 31;
    if (dst >= NN) return;
    int start = g_off[dst], end = g_off[dst + 1];
    float edv = g_ed2[dst];

    float m = -1e30f, s = 0.f;
    for (int j = start + lane; j < end; j += 32) {
        int src = g_esrc[j];
        float e = lrelu(g_es2[src] + edv);
        float n = fmaxf(m, e); s = s*__expf(m-n) + __expf(e-n); m = n;
    }
    #pragma unroll
    for (int off = 16; off; off >>= 1) {
        float mo = __shfl_xor_sync(0xffffffffu, m, off);
        float so = __shfl_xor_sync(0xffffffffu, s, off);
        float n = fmaxf(m, mo); s = s*__expf(m-n) + so*__expf(mo-n); m = n;
    }
    float inv = 1.f / s;

    float4 acc = make_float4(0.f,0.f,0.f,0.f);
    #pragma unroll 4
    for (int j = start; j < end; j++) {
        int src = g_esrc[j];
        float e = lrelu(g_es2[src] + edv);
        float wt = __expf(e - m) * inv;
        const float2* row = (const float2*)(g_h2h + (size_t)src * H2DIM);
        float2 q = row[lane];
        float2 f0 = __half22float2(*(__half2*)&q.x);
        float2 f1 = __half22float2(*(__half2*)&q.y);
        acc.x = fmaf(wt, f0.x, acc.x); acc.y = fmaf(wt, f0.y, acc.y);
        acc.z = fmaf(wt, f1.x, acc.z); acc.w = fmaf(wt, f1.y, acc.w);
    }

    int c0 = lane * 4;
    float4 bb = *(const float4*)&b2[c0];
    float4 o = make_float4(elu1(acc.x + bb.x), elu1(acc.y + bb.y),
                           elu1(acc.z + bb.z), elu1(acc.w + bb.w));
    *(float4*)(g_out2 + (size_t)dst * H2DIM + c0) = o;
}

// ---------------- pooling + FC + log_softmax ---------------------------------
__device__ __forceinline__ int lb_i(const int* a, int n, int v) {
    int lo = 0, hi = n;
    while (lo < hi) { int mid = (lo + hi) >> 1; if (a[mid] < v) lo = mid + 1; else hi = mid; }
    return lo;
}

__global__ void pool_fc_kernel(const int* __restrict__ batch,
                               const float* __restrict__ fc_w,
                               const float* __restrict__ fc_b,
                               float* __restrict__ out)
{
    int g = blockIdx.x;
    int tid = threadIdx.x;
    __shared__ float sp[128];
    __shared__ float slog[10];
    int lo = lb_i(batch, NN, g);
    int hi = lb_i(batch, NN, g + 1);
    float s = 0.f;
    for (int i = lo; i < hi; i++) s += g_out2[(size_t)i * H2DIM + tid];
    float cnt = (float)(hi - lo);
    sp[tid] = s / fmaxf(cnt, 1.f);
    __syncthreads();
    if (tid < 10) {
        float l = fc_b[tid];
        #pragma unroll 16
        for (int c = 0; c < 128; c++) l = fmaf(sp[c], fc_w[c * 10 + tid], l);
        slog[tid] = l;
    }
    __syncthreads();
    if (tid == 0) {
        float mx = -1e30f;
        #pragma unroll
        for (int k = 0; k < 10; k++) mx = fmaxf(mx, slog[k]);
        float sum = 0.f;
        #pragma unroll
        for (int k = 0; k < 10; k++) sum += expf(slog[k] - mx);
        float lse = mx + logf(sum);
        #pragma unroll
        for (int k = 0; k < 10; k++) out[g * 10 + k] = slog[k] - lse;
    }
}

// ---------------- launch -----------------------------------------------------
extern "C" void kernel_launch(void* const* d_in, const int* in_sizes, int n_in,
                              void* d_out, int out_size)
{
    const float* x     = (const float*)d_in[0];
    const int*   ei    = (const int*)d_in[1];
    const int*   batch = (const int*)d_in[2];
    const float* W1    = (const float*)d_in[3];
    const float* a_s1  = (const float*)d_in[4];
    const float* a_d1  = (const float*)d_in[5];
    const float* b1    = (const float*)d_in[6];
    const float* W2    = (const float*)d_in[7];
    const float* a_s2  = (const float*)d_in[8];
    const float* a_d2  = (const float*)d_in[9];
    const float* b2    = (const float*)d_in[10];
    const float* fc_w  = (const float*)d_in[11];
    const float* fc_b  = (const float*)d_in[12];
    float* out = (float*)d_out;

    zero_counts_kernel<<<(NN + 255) / 256, 256>>>();
    count_kernel<<<(ET + 255) / 256, 256>>>(ei);
    scan1_kernel<<<NBLK, 1024>>>();
    scan2_kernel<<<1, 64>>>();
    scan3_kernel<<<(NN + 255) / 256, 256>>>();
    fill_kernel<<<(ET + 255) / 256, 256>>>(ei);

    {
        dim3 grid(H1DIM / BN, (NN + BM - 1) / BM);
        gemm1_kernel<<<grid, 256>>>(x, W1);
    }
    coef1_kernel<<<(NN * 4 + 255) / 256, 256>>>(a_s1, a_d1);
    agg1_kernel<<<(NN * 32 + 255) / 256, 256>>>(b1);

    {
        dim3 grid(H2DIM / BN, (NN + BM - 1) / BM);
        gemm2_kernel<<<grid, 256>>>(W2);
    }
    coef2_kernel<<<(NN + 255) / 256, 256>>>(a_s2, a_d2);
    agg2_kernel<<<(NN * 32 + 255) / 256, 256>>>(b2);

    pool_fc_kernel<<<NGRAPH, 128>>>(batch, fc_w, fc_b, out);
}